// round 1
// baseline (speedup 1.0000x reference)
#include <cuda_runtime.h>
#include <math.h>

#define SEQ   2048
#define HID   2048
#define HD    128
#define NH    16

// Scratch (device globals: allocation-free rule)
__device__ float g_Q[SEQ * HID];
__device__ float g_K[SEQ * HID];
__device__ float g_V[SEQ * HID];
__device__ float g_O[SEQ * HID];

// ---------------------------------------------------------------------------
// SGEMM:  C[M,N] = A[M,K] @ B[N,K]^T + bias[N]     (both operands K-contiguous)
// Block 128x128, thread 8x8, K-step 16, 256 threads.
// ---------------------------------------------------------------------------
#define BM 128
#define BN 128
#define BK 16

__global__ __launch_bounds__(256) void sgemm_nt_bias(
    const float* __restrict__ A, const float* __restrict__ B,
    const float* __restrict__ bias, float* __restrict__ C)
{
    __shared__ float As[BK][BM];
    __shared__ float Bs[BK][BN];

    const int tid  = threadIdx.x;
    const int tx   = tid & 15;        // 0..15
    const int ty   = tid >> 4;        // 0..15
    const int row0 = blockIdx.y * BM;
    const int col0 = blockIdx.x * BN;
    const int lr   = tid >> 2;        // 0..63
    const int lc   = (tid & 3) << 2;  // 0,4,8,12

    float acc[8][8];
#pragma unroll
    for (int i = 0; i < 8; i++)
#pragma unroll
        for (int j = 0; j < 8; j++) acc[i][j] = 0.0f;

    for (int k0 = 0; k0 < HID; k0 += BK) {
#pragma unroll
        for (int h = 0; h < 2; h++) {
            const int r = lr + h * 64;
            float4 va = *(const float4*)&A[(size_t)(row0 + r) * HID + k0 + lc];
            As[lc + 0][r] = va.x; As[lc + 1][r] = va.y;
            As[lc + 2][r] = va.z; As[lc + 3][r] = va.w;
            float4 vb = *(const float4*)&B[(size_t)(col0 + r) * HID + k0 + lc];
            Bs[lc + 0][r] = vb.x; Bs[lc + 1][r] = vb.y;
            Bs[lc + 2][r] = vb.z; Bs[lc + 3][r] = vb.w;
        }
        __syncthreads();

#pragma unroll
        for (int k = 0; k < BK; k++) {
            float a[8], b[8];
            *(float4*)&a[0] = *(const float4*)&As[k][ty * 8];
            *(float4*)&a[4] = *(const float4*)&As[k][ty * 8 + 4];
            *(float4*)&b[0] = *(const float4*)&Bs[k][tx * 8];
            *(float4*)&b[4] = *(const float4*)&Bs[k][tx * 8 + 4];
#pragma unroll
            for (int i = 0; i < 8; i++)
#pragma unroll
                for (int j = 0; j < 8; j++)
                    acc[i][j] = fmaf(a[i], b[j], acc[i][j]);
        }
        __syncthreads();
    }

    float bcol[8];
    *(float4*)&bcol[0] = *(const float4*)&bias[col0 + tx * 8];
    *(float4*)&bcol[4] = *(const float4*)&bias[col0 + tx * 8 + 4];

#pragma unroll
    for (int i = 0; i < 8; i++) {
        float* crow = &C[(size_t)(row0 + ty * 8 + i) * HID + col0 + tx * 8];
        float4 c0 = make_float4(acc[i][0] + bcol[0], acc[i][1] + bcol[1],
                                acc[i][2] + bcol[2], acc[i][3] + bcol[3]);
        float4 c1 = make_float4(acc[i][4] + bcol[4], acc[i][5] + bcol[5],
                                acc[i][6] + bcol[6], acc[i][7] + bcol[7]);
        *(float4*)&crow[0] = c0;
        *(float4*)&crow[4] = c1;
    }
}

// ---------------------------------------------------------------------------
// Flash attention, fp32. One block = 64 queries x 1 head. 256 threads (16x16).
// Effective math:
//   attn = softmax( alpha * (q.k)  +  obias * k_idx ),  alpha=(1-0.1*sig(j))/sqrt(hd)
//   O = attn @ V
// smem (dynamic): Qs[128][68] + Ks[128][68] + Vs[64][128] + Ps[64][68]
// ---------------------------------------------------------------------------
#define AQ 64
#define AK 64
#define QPITCH 68

#define QS_OFF  0
#define KS_OFF  (128 * QPITCH)
#define VS_OFF  (2 * 128 * QPITCH)
#define PS_OFF  (2 * 128 * QPITCH + AK * HD)
#define ATT_SMEM_FLOATS (2 * 128 * QPITCH + AK * HD + AQ * QPITCH)
#define ATT_SMEM_BYTES  (ATT_SMEM_FLOATS * 4)

__global__ __launch_bounds__(256) void flash_attn_f32(
    const float* __restrict__ Q, const float* __restrict__ K,
    const float* __restrict__ V, float* __restrict__ O,
    const float* __restrict__ order_gate, const float* __restrict__ justice_gate)
{
    extern __shared__ float sm[];
    float* Qs = sm + QS_OFF;   // [128][QPITCH] transposed: Qs[d][q]
    float* Ks = sm + KS_OFF;   // [128][QPITCH] transposed: Ks[d][k]
    float* Vs = sm + VS_OFF;   // [AK][HD] row-major
    float* Ps = sm + PS_OFF;   // [AQ][QPITCH]

    const int tid = threadIdx.x;
    const int tx  = tid & 15;   // k-cols (scores) / d-col group (out)
    const int ty  = tid >> 4;   // q-row group
    const int h   = blockIdx.y;
    const int q0  = blockIdx.x * AQ;
    const int hcol = h * HD;

    const float sig_j = 1.0f / (1.0f + __expf(-justice_gate[0]));
    const float sig_o = 1.0f / (1.0f + __expf(-order_gate[0]));
    const float alpha = (1.0f - 0.1f * sig_j) * rsqrtf((float)HD);
    const float obias = sig_o * 0.05f / (float)SEQ;

    // Load Q tile, transposed
    for (int i = tid; i < AQ * 32; i += 256) {
        const int row = i >> 5;
        const int d4  = (i & 31) << 2;
        float4 v = *(const float4*)&Q[(size_t)(q0 + row) * HID + hcol + d4];
        Qs[(d4 + 0) * QPITCH + row] = v.x;
        Qs[(d4 + 1) * QPITCH + row] = v.y;
        Qs[(d4 + 2) * QPITCH + row] = v.z;
        Qs[(d4 + 3) * QPITCH + row] = v.w;
    }

    float m_i[4], l_i[4];
    float acc[4][8];
#pragma unroll
    for (int i = 0; i < 4; i++) {
        m_i[i] = -1.0e30f; l_i[i] = 0.0f;
#pragma unroll
        for (int j = 0; j < 8; j++) acc[i][j] = 0.0f;
    }

    for (int kt = 0; kt < SEQ; kt += AK) {
        // Load K tile (transposed) and V tile
        for (int i = tid; i < AK * 32; i += 256) {
            const int row = i >> 5;
            const int d4  = (i & 31) << 2;
            float4 kv = *(const float4*)&K[(size_t)(kt + row) * HID + hcol + d4];
            Ks[(d4 + 0) * QPITCH + row] = kv.x;
            Ks[(d4 + 1) * QPITCH + row] = kv.y;
            Ks[(d4 + 2) * QPITCH + row] = kv.z;
            Ks[(d4 + 3) * QPITCH + row] = kv.w;
            float4 vv = *(const float4*)&V[(size_t)(kt + row) * HID + hcol + d4];
            *(float4*)&Vs[row * HD + d4] = vv;
        }
        __syncthreads();

        // scores s[4][4] = q.k
        float s[4][4];
#pragma unroll
        for (int i = 0; i < 4; i++)
#pragma unroll
            for (int j = 0; j < 4; j++) s[i][j] = 0.0f;

#pragma unroll 4
        for (int d = 0; d < HD; d++) {
            float4 a = *(const float4*)&Qs[d * QPITCH + ty * 4];
            float4 b = *(const float4*)&Ks[d * QPITCH + tx * 4];
            const float av[4] = {a.x, a.y, a.z, a.w};
            const float bv[4] = {b.x, b.y, b.z, b.w};
#pragma unroll
            for (int i = 0; i < 4; i++)
#pragma unroll
                for (int j = 0; j < 4; j++)
                    s[i][j] = fmaf(av[i], bv[j], s[i][j]);
        }

        // scale + key position bias
#pragma unroll
        for (int i = 0; i < 4; i++)
#pragma unroll
            for (int j = 0; j < 4; j++)
                s[i][j] = fmaf(s[i][j], alpha, obias * (float)(kt + tx * 4 + j));

        // online softmax update (row stats across the 16 tx lanes)
#pragma unroll
        for (int i = 0; i < 4; i++) {
            float rmax = fmaxf(fmaxf(s[i][0], s[i][1]), fmaxf(s[i][2], s[i][3]));
#pragma unroll
            for (int off = 1; off < 16; off <<= 1)
                rmax = fmaxf(rmax, __shfl_xor_sync(0xffffffffu, rmax, off));
            const float m_new = fmaxf(m_i[i], rmax);
            const float corr  = __expf(m_i[i] - m_new);
            float rsum = 0.0f;
#pragma unroll
            for (int j = 0; j < 4; j++) {
                s[i][j] = __expf(s[i][j] - m_new);
                rsum += s[i][j];
            }
#pragma unroll
            for (int off = 1; off < 16; off <<= 1)
                rsum += __shfl_xor_sync(0xffffffffu, rsum, off);
            l_i[i] = l_i[i] * corr + rsum;
            m_i[i] = m_new;
#pragma unroll
            for (int j = 0; j < 8; j++) acc[i][j] *= corr;
            // stash P row
            *(float4*)&Ps[(ty * 4 + i) * QPITCH + tx * 4] =
                make_float4(s[i][0], s[i][1], s[i][2], s[i][3]);
        }
        __syncthreads();

        // O += P @ V     (thread covers q rows ty*4.., d cols j*16+tx)
#pragma unroll 4
        for (int k = 0; k < AK; k++) {
            float a[4], b[8];
#pragma unroll
            for (int i = 0; i < 4; i++) a[i] = Ps[(ty * 4 + i) * QPITCH + k];
#pragma unroll
            for (int j = 0; j < 8; j++) b[j] = Vs[k * HD + j * 16 + tx];
#pragma unroll
            for (int i = 0; i < 4; i++)
#pragma unroll
                for (int j = 0; j < 8; j++)
                    acc[i][j] = fmaf(a[i], b[j], acc[i][j]);
        }
        __syncthreads();
    }

    // normalize + write
#pragma unroll
    for (int i = 0; i < 4; i++) {
        const float inv_l = 1.0f / l_i[i];
        float* orow = &O[(size_t)(q0 + ty * 4 + i) * HID + hcol];
#pragma unroll
        for (int j = 0; j < 8; j++)
            orow[j * 16 + tx] = acc[i][j] * inv_l;
    }
}

// ---------------------------------------------------------------------------
extern "C" void kernel_launch(void* const* d_in, const int* in_sizes, int n_in,
                              void* d_out, int out_size)
{
    const float* X  = (const float*)d_in[0];
    const float* Wq = (const float*)d_in[1];
    const float* bq = (const float*)d_in[2];
    const float* Wk = (const float*)d_in[3];
    const float* bk = (const float*)d_in[4];
    const float* Wv = (const float*)d_in[5];
    const float* bv = (const float*)d_in[6];
    const float* Wo = (const float*)d_in[7];
    const float* bo = (const float*)d_in[8];
    const float* order_gate   = (const float*)d_in[11];
    const float* justice_gate = (const float*)d_in[12];
    float* out = (float*)d_out;

    float *qp, *kp, *vp, *op;
    cudaGetSymbolAddress((void**)&qp, g_Q);
    cudaGetSymbolAddress((void**)&kp, g_K);
    cudaGetSymbolAddress((void**)&vp, g_V);
    cudaGetSymbolAddress((void**)&op, g_O);

    cudaFuncSetAttribute(flash_attn_f32,
                         cudaFuncAttributeMaxDynamicSharedMemorySize,
                         ATT_SMEM_BYTES);

    dim3 gg(HID / BN, SEQ / BM);
    sgemm_nt_bias<<<gg, 256>>>(X, Wq, bq, qp);
    sgemm_nt_bias<<<gg, 256>>>(X, Wk, bk, kp);
    sgemm_nt_bias<<<gg, 256>>>(X, Wv, bv, vp);

    dim3 ga(SEQ / AQ, NH);
    flash_attn_f32<<<ga, 256, ATT_SMEM_BYTES>>>(qp, kp, vp, op,
                                                order_gate, justice_gate);

    sgemm_nt_bias<<<gg, 256>>>(op, Wo, bo, out);
}

// round 3
// speedup vs baseline: 1.4965x; 1.4965x over previous
#include <cuda_runtime.h>
#include <math.h>
#include <stdint.h>

#define SEQ   2048
#define HID   2048
#define HD    128
#define NH    16

// Scratch (device globals: allocation-free rule)
__device__ float g_Q[SEQ * HID];
__device__ float g_K[SEQ * HID];
__device__ float g_V[SEQ * HID];
__device__ float g_O[SEQ * HID];

// ===========================================================================
// Helpers
// ===========================================================================
__device__ __forceinline__ uint32_t smem_u32(const void* p) {
    uint32_t a;
    asm("{ .reg .u64 t; cvta.to.shared.u64 t, %1; cvt.u32.u64 %0, t; }"
        : "=r"(a) : "l"(p));
    return a;
}
__device__ __forceinline__ void cp_async16(uint32_t dst, const void* src) {
    asm volatile("cp.async.cg.shared.global [%0], [%1], 16;" :: "r"(dst), "l"(src));
}
#define CP_COMMIT() asm volatile("cp.async.commit_group;" ::: "memory")
#define CP_WAIT(n)  asm volatile("cp.async.wait_group %0;" :: "n"(n) : "memory")

__device__ __forceinline__ uint32_t f2tf(float x) {
    uint32_t r;
    asm("cvt.rna.tf32.f32 %0, %1;" : "=r"(r) : "f"(x));
    return r;
}

// C[16x8] += A[16x8] * B[8x8]^T   (tf32, fp32 accum)
__device__ __forceinline__ void mma_tf32(float c[4], const uint32_t a[4],
                                         const uint32_t b[2]) {
    asm volatile(
        "mma.sync.aligned.m16n8k8.row.col.f32.tf32.tf32.f32 "
        "{%0,%1,%2,%3}, {%4,%5,%6,%7}, {%8,%9}, {%0,%1,%2,%3};"
        : "+f"(c[0]), "+f"(c[1]), "+f"(c[2]), "+f"(c[3])
        : "r"(a[0]), "r"(a[1]), "r"(a[2]), "r"(a[3]), "r"(b[0]), "r"(b[1]));
}

// ===========================================================================
// tf32 mma.sync GEMM:  C[M,N] = A[M,K] @ B[N,K]^T + bias[N]
// CTA 128x128, 8 warps (2x4) of 64x32, BK=16, 3-stage cp.async.
// Smem rows padded to 20 floats -> conflict-free scalar fragment loads.
// ===========================================================================
#define BM 128
#define BN 128
#define BK 16
#define NST 3
#define ROWP 20
#define AT_FLOATS (BM * ROWP)                 // 2560
#define STAGE_FLOATS (2 * AT_FLOATS)          // 5120
#define GEMM_SMEM_BYTES (NST * STAGE_FLOATS * 4)   // 61440

__device__ __forceinline__ void gemm_load_stage(
    const float* __restrict__ Ab, const float* __restrict__ Bb,
    float* sm, int slot, int k0, int tid)
{
    float* As = sm + slot * STAGE_FLOATS;
    float* Bs = As + AT_FLOATS;
    const uint32_t sa = smem_u32(As);
    const uint32_t sb = smem_u32(Bs);
#pragma unroll
    for (int it = 0; it < 2; it++) {
        const int idx = tid + it * 256;       // 0..511
        const int r = idx >> 2;
        const int q = idx & 3;
        const uint32_t off = (uint32_t)(r * ROWP + q * 4) * 4u;
        cp_async16(sa + off, Ab + (size_t)r * HID + k0 + q * 4);
        cp_async16(sb + off, Bb + (size_t)r * HID + k0 + q * 4);
    }
}

__global__ __launch_bounds__(256) void gemm_tf32_mma(
    const float* __restrict__ A, const float* __restrict__ B,
    const float* __restrict__ bias, float* __restrict__ C)
{
    extern __shared__ float sm[];

    const int tid  = threadIdx.x;
    const int wid  = tid >> 5;
    const int lane = tid & 31;
    const int lr   = lane >> 2;      // 0..7
    const int lc   = lane & 3;       // 0..3
    const int wm   = (wid >> 2) * 64;    // warp M offset in tile
    const int wn   = (wid & 3) * 32;     // warp N offset in tile
    const int row0 = blockIdx.y * BM;
    const int col0 = blockIdx.x * BN;

    const float* Ab = A + (size_t)row0 * HID;
    const float* Bb = B + (size_t)col0 * HID;

    float acc[4][4][4];
#pragma unroll
    for (int mt = 0; mt < 4; mt++)
#pragma unroll
        for (int nt = 0; nt < 4; nt++)
#pragma unroll
            for (int i = 0; i < 4; i++) acc[mt][nt][i] = 0.0f;

    // prologue: fill NST-1 stages
#pragma unroll
    for (int s = 0; s < NST - 1; s++) {
        gemm_load_stage(Ab, Bb, sm, s, s * BK, tid);
        CP_COMMIT();
    }

    const int KCH = HID / BK;   // 128
    for (int j = 0; j < KCH; j++) {
        // issue load for chunk j+NST-1 into slot (j-1)%NST (synced last iter)
        if (j + NST - 1 < KCH) {
            gemm_load_stage(Ab, Bb, sm, (j + NST - 1) % NST, (j + NST - 1) * BK, tid);
        }
        CP_COMMIT();
        CP_WAIT(NST - 1);      // chunk j resident
        __syncthreads();

        const float* As = sm + (j % NST) * STAGE_FLOATS;
        const float* Bs = As + AT_FLOATS;

#pragma unroll
        for (int kk = 0; kk < BK; kk += 8) {
            uint32_t af[4][4], bf[4][2];
#pragma unroll
            for (int mt = 0; mt < 4; mt++) {
                const float* ap = As + (wm + mt * 16 + lr) * ROWP + kk + lc;
                af[mt][0] = f2tf(ap[0]);
                af[mt][1] = f2tf(ap[8 * ROWP]);
                af[mt][2] = f2tf(ap[4]);
                af[mt][3] = f2tf(ap[8 * ROWP + 4]);
            }
#pragma unroll
            for (int nt = 0; nt < 4; nt++) {
                const float* bp = Bs + (wn + nt * 8 + lr) * ROWP + kk + lc;
                bf[nt][0] = f2tf(bp[0]);
                bf[nt][1] = f2tf(bp[4]);
            }
#pragma unroll
            for (int mt = 0; mt < 4; mt++)
#pragma unroll
                for (int nt = 0; nt < 4; nt++)
                    mma_tf32(acc[mt][nt], af[mt], bf[nt]);
        }
        __syncthreads();
    }

    // epilogue: bias + store (float2 per c-pair)
#pragma unroll
    for (int mt = 0; mt < 4; mt++) {
#pragma unroll
        for (int half = 0; half < 2; half++) {
            const int r = row0 + wm + mt * 16 + lr + half * 8;
            float* crow = C + (size_t)r * HID;
#pragma unroll
            for (int nt = 0; nt < 4; nt++) {
                const int c = col0 + wn + nt * 8 + 2 * lc;
                float2 v;
                v.x = acc[mt][nt][half * 2 + 0] + bias[c];
                v.y = acc[mt][nt][half * 2 + 1] + bias[c + 1];
                *(float2*)(crow + c) = v;
            }
        }
    }
}

// ===========================================================================
// Flash attention, fp32 (unchanged — known good)
// ===========================================================================
#define AQ 64
#define AK 64
#define QPITCH 68
#define QS_OFF  0
#define KS_OFF  (128 * QPITCH)
#define VS_OFF  (2 * 128 * QPITCH)
#define PS_OFF  (2 * 128 * QPITCH + AK * HD)
#define ATT_SMEM_FLOATS (2 * 128 * QPITCH + AK * HD + AQ * QPITCH)
#define ATT_SMEM_BYTES  (ATT_SMEM_FLOATS * 4)

__global__ __launch_bounds__(256) void flash_attn_f32(
    const float* __restrict__ Q, const float* __restrict__ K,
    const float* __restrict__ V, float* __restrict__ O,
    const float* __restrict__ order_gate, const float* __restrict__ justice_gate)
{
    extern __shared__ float smf[];
    float* Qs = smf + QS_OFF;
    float* Ks = smf + KS_OFF;
    float* Vs = smf + VS_OFF;
    float* Ps = smf + PS_OFF;

    const int tid = threadIdx.x;
    const int tx  = tid & 15;
    const int ty  = tid >> 4;
    const int h   = blockIdx.y;
    const int q0  = blockIdx.x * AQ;
    const int hcol = h * HD;

    const float sig_j = 1.0f / (1.0f + __expf(-justice_gate[0]));
    const float sig_o = 1.0f / (1.0f + __expf(-order_gate[0]));
    const float alpha = (1.0f - 0.1f * sig_j) * rsqrtf((float)HD);
    const float obias = sig_o * 0.05f / (float)SEQ;

    for (int i = tid; i < AQ * 32; i += 256) {
        const int row = i >> 5;
        const int d4  = (i & 31) << 2;
        float4 v = *(const float4*)&Q[(size_t)(q0 + row) * HID + hcol + d4];
        Qs[(d4 + 0) * QPITCH + row] = v.x;
        Qs[(d4 + 1) * QPITCH + row] = v.y;
        Qs[(d4 + 2) * QPITCH + row] = v.z;
        Qs[(d4 + 3) * QPITCH + row] = v.w;
    }

    float m_i[4], l_i[4];
    float acc[4][8];
#pragma unroll
    for (int i = 0; i < 4; i++) {
        m_i[i] = -1.0e30f; l_i[i] = 0.0f;
#pragma unroll
        for (int j = 0; j < 8; j++) acc[i][j] = 0.0f;
    }

    for (int kt = 0; kt < SEQ; kt += AK) {
        for (int i = tid; i < AK * 32; i += 256) {
            const int row = i >> 5;
            const int d4  = (i & 31) << 2;
            float4 kv = *(const float4*)&K[(size_t)(kt + row) * HID + hcol + d4];
            Ks[(d4 + 0) * QPITCH + row] = kv.x;
            Ks[(d4 + 1) * QPITCH + row] = kv.y;
            Ks[(d4 + 2) * QPITCH + row] = kv.z;
            Ks[(d4 + 3) * QPITCH + row] = kv.w;
            float4 vv = *(const float4*)&V[(size_t)(kt + row) * HID + hcol + d4];
            *(float4*)&Vs[row * HD + d4] = vv;
        }
        __syncthreads();

        float s[4][4];
#pragma unroll
        for (int i = 0; i < 4; i++)
#pragma unroll
            for (int j = 0; j < 4; j++) s[i][j] = 0.0f;

#pragma unroll 4
        for (int d = 0; d < HD; d++) {
            float4 a = *(const float4*)&Qs[d * QPITCH + ty * 4];
            float4 b = *(const float4*)&Ks[d * QPITCH + tx * 4];
            const float av[4] = {a.x, a.y, a.z, a.w};
            const float bv[4] = {b.x, b.y, b.z, b.w};
#pragma unroll
            for (int i = 0; i < 4; i++)
#pragma unroll
                for (int j = 0; j < 4; j++)
                    s[i][j] = fmaf(av[i], bv[j], s[i][j]);
        }

#pragma unroll
        for (int i = 0; i < 4; i++)
#pragma unroll
            for (int j = 0; j < 4; j++)
                s[i][j] = fmaf(s[i][j], alpha, obias * (float)(kt + tx * 4 + j));

#pragma unroll
        for (int i = 0; i < 4; i++) {
            float rmax = fmaxf(fmaxf(s[i][0], s[i][1]), fmaxf(s[i][2], s[i][3]));
#pragma unroll
            for (int off = 1; off < 16; off <<= 1)
                rmax = fmaxf(rmax, __shfl_xor_sync(0xffffffffu, rmax, off));
            const float m_new = fmaxf(m_i[i], rmax);
            const float corr  = __expf(m_i[i] - m_new);
            float rsum = 0.0f;
#pragma unroll
            for (int j = 0; j < 4; j++) {
                s[i][j] = __expf(s[i][j] - m_new);
                rsum += s[i][j];
            }
#pragma unroll
            for (int off = 1; off < 16; off <<= 1)
                rsum += __shfl_xor_sync(0xffffffffu, rsum, off);
            l_i[i] = l_i[i] * corr + rsum;
            m_i[i] = m_new;
#pragma unroll
            for (int j = 0; j < 8; j++) acc[i][j] *= corr;
            *(float4*)&Ps[(ty * 4 + i) * QPITCH + tx * 4] =
                make_float4(s[i][0], s[i][1], s[i][2], s[i][3]);
        }
        __syncthreads();

#pragma unroll 4
        for (int k = 0; k < AK; k++) {
            float a[4], b[8];
#pragma unroll
            for (int i = 0; i < 4; i++) a[i] = Ps[(ty * 4 + i) * QPITCH + k];
#pragma unroll
            for (int j = 0; j < 8; j++) b[j] = Vs[k * HD + j * 16 + tx];
#pragma unroll
            for (int i = 0; i < 4; i++)
#pragma unroll
                for (int j = 0; j < 8; j++)
                    acc[i][j] = fmaf(a[i], b[j], acc[i][j]);
        }
        __syncthreads();
    }

#pragma unroll
    for (int i = 0; i < 4; i++) {
        const float inv_l = 1.0f / l_i[i];
        float* orow = &O[(size_t)(q0 + ty * 4 + i) * HID + hcol];
#pragma unroll
        for (int j = 0; j < 8; j++)
            orow[j * 16 + tx] = acc[i][j] * inv_l;
    }
}

// ===========================================================================
extern "C" void kernel_launch(void* const* d_in, const int* in_sizes, int n_in,
                              void* d_out, int out_size)
{
    const float* X  = (const float*)d_in[0];
    const float* Wq = (const float*)d_in[1];
    const float* bq = (const float*)d_in[2];
    const float* Wk = (const float*)d_in[3];
    const float* bk = (const float*)d_in[4];
    const float* Wv = (const float*)d_in[5];
    const float* bv = (const float*)d_in[6];
    const float* Wo = (const float*)d_in[7];
    const float* bo = (const float*)d_in[8];
    const float* order_gate   = (const float*)d_in[11];
    const float* justice_gate = (const float*)d_in[12];
    float* out = (float*)d_out;

    float *qp, *kp, *vp, *op;
    cudaGetSymbolAddress((void**)&qp, g_Q);
    cudaGetSymbolAddress((void**)&kp, g_K);
    cudaGetSymbolAddress((void**)&vp, g_V);
    cudaGetSymbolAddress((void**)&op, g_O);

    cudaFuncSetAttribute(gemm_tf32_mma,
                         cudaFuncAttributeMaxDynamicSharedMemorySize,
                         GEMM_SMEM_BYTES);
    cudaFuncSetAttribute(flash_attn_f32,
                         cudaFuncAttributeMaxDynamicSharedMemorySize,
                         ATT_SMEM_BYTES);

    dim3 gg(HID / BN, SEQ / BM);   // 16 x 16
    gemm_tf32_mma<<<gg, 256, GEMM_SMEM_BYTES>>>(X, Wq, bq, qp);
    gemm_tf32_mma<<<gg, 256, GEMM_SMEM_BYTES>>>(X, Wk, bk, kp);
    gemm_tf32_mma<<<gg, 256, GEMM_SMEM_BYTES>>>(X, Wv, bv, vp);

    dim3 ga(SEQ / AQ, NH);
    flash_attn_f32<<<ga, 256, ATT_SMEM_BYTES>>>(qp, kp, vp, op,
                                                order_gate, justice_gate);

    gemm_tf32_mma<<<gg, 256, GEMM_SMEM_BYTES>>>(op, Wo, bo, out);
}

// round 4
// speedup vs baseline: 3.7688x; 2.5184x over previous
#include <cuda_runtime.h>
#include <math.h>
#include <stdint.h>

#define SEQ   2048
#define HID   2048
#define HD    128
#define NH    16

// Scratch (device globals: allocation-free rule)
__device__ float g_Q[SEQ * HID];
__device__ float g_K[SEQ * HID];
__device__ float g_V[SEQ * HID];
__device__ float g_O[SEQ * HID];

// ===========================================================================
// Helpers
// ===========================================================================
__device__ __forceinline__ uint32_t smem_u32(const void* p) {
    uint32_t a;
    asm("{ .reg .u64 t; cvta.to.shared.u64 t, %1; cvt.u32.u64 %0, t; }"
        : "=r"(a) : "l"(p));
    return a;
}
__device__ __forceinline__ void cp_async16(uint32_t dst, const void* src) {
    asm volatile("cp.async.cg.shared.global [%0], [%1], 16;" :: "r"(dst), "l"(src));
}
#define CP_COMMIT() asm volatile("cp.async.commit_group;" ::: "memory")
#define CP_WAIT(n)  asm volatile("cp.async.wait_group %0;" :: "n"(n) : "memory")

__device__ __forceinline__ uint32_t f2tf(float x) {
    uint32_t r;
    asm("cvt.rna.tf32.f32 %0, %1;" : "=r"(r) : "f"(x));
    return r;
}
__device__ __forceinline__ uint32_t shfl_u32(uint32_t v, int src) {
    return __shfl_sync(0xffffffffu, v, src);
}

// C[16x8] += A[16x8] * B[8x8]^T   (tf32, fp32 accum)
__device__ __forceinline__ void mma_tf32(float c[4], const uint32_t a[4],
                                         const uint32_t b[2]) {
    asm volatile(
        "mma.sync.aligned.m16n8k8.row.col.f32.tf32.tf32.f32 "
        "{%0,%1,%2,%3}, {%4,%5,%6,%7}, {%8,%9}, {%0,%1,%2,%3};"
        : "+f"(c[0]), "+f"(c[1]), "+f"(c[2]), "+f"(c[3])
        : "r"(a[0]), "r"(a[1]), "r"(a[2]), "r"(a[3]), "r"(b[0]), "r"(b[1]));
}

// ===========================================================================
// tf32 mma.sync GEMM:  C[M,N] = A[M,K] @ B[N,K]^T + bias[N]
// CTA 128x128, 8 warps (2x4) of 64x32, BK=16, 3-stage cp.async.
// RND: round output to tf32 (rna) on store (for Q/K/V feeding attention MMAs).
// ===========================================================================
#define BM 128
#define BN 128
#define BK 16
#define NST 3
#define ROWP 20
#define AT_FLOATS (BM * ROWP)                 // 2560
#define STAGE_FLOATS (2 * AT_FLOATS)          // 5120
#define GEMM_SMEM_BYTES (NST * STAGE_FLOATS * 4)   // 61440

__device__ __forceinline__ void gemm_load_stage(
    const float* __restrict__ Ab, const float* __restrict__ Bb,
    float* sm, int slot, int k0, int tid)
{
    float* As = sm + slot * STAGE_FLOATS;
    float* Bs = As + AT_FLOATS;
    const uint32_t sa = smem_u32(As);
    const uint32_t sb = smem_u32(Bs);
#pragma unroll
    for (int it = 0; it < 2; it++) {
        const int idx = tid + it * 256;       // 0..511
        const int r = idx >> 2;
        const int q = idx & 3;
        const uint32_t off = (uint32_t)(r * ROWP + q * 4) * 4u;
        cp_async16(sa + off, Ab + (size_t)r * HID + k0 + q * 4);
        cp_async16(sb + off, Bb + (size_t)r * HID + k0 + q * 4);
    }
}

template <bool RND>
__global__ __launch_bounds__(256) void gemm_tf32_mma(
    const float* __restrict__ A, const float* __restrict__ B,
    const float* __restrict__ bias, float* __restrict__ C)
{
    extern __shared__ float sm[];

    const int tid  = threadIdx.x;
    const int wid  = tid >> 5;
    const int lane = tid & 31;
    const int lr   = lane >> 2;
    const int lc   = lane & 3;
    const int wm   = (wid >> 2) * 64;
    const int wn   = (wid & 3) * 32;
    const int row0 = blockIdx.y * BM;
    const int col0 = blockIdx.x * BN;

    const float* Ab = A + (size_t)row0 * HID;
    const float* Bb = B + (size_t)col0 * HID;

    float acc[4][4][4];
#pragma unroll
    for (int mt = 0; mt < 4; mt++)
#pragma unroll
        for (int nt = 0; nt < 4; nt++)
#pragma unroll
            for (int i = 0; i < 4; i++) acc[mt][nt][i] = 0.0f;

#pragma unroll
    for (int s = 0; s < NST - 1; s++) {
        gemm_load_stage(Ab, Bb, sm, s, s * BK, tid);
        CP_COMMIT();
    }

    const int KCH = HID / BK;   // 128
    for (int j = 0; j < KCH; j++) {
        if (j + NST - 1 < KCH) {
            gemm_load_stage(Ab, Bb, sm, (j + NST - 1) % NST, (j + NST - 1) * BK, tid);
        }
        CP_COMMIT();
        CP_WAIT(NST - 1);
        __syncthreads();

        const float* As = sm + (j % NST) * STAGE_FLOATS;
        const float* Bs = As + AT_FLOATS;

#pragma unroll
        for (int kk = 0; kk < BK; kk += 8) {
            uint32_t af[4][4], bf[4][2];
#pragma unroll
            for (int mt = 0; mt < 4; mt++) {
                const float* ap = As + (wm + mt * 16 + lr) * ROWP + kk + lc;
                af[mt][0] = f2tf(ap[0]);
                af[mt][1] = f2tf(ap[8 * ROWP]);
                af[mt][2] = f2tf(ap[4]);
                af[mt][3] = f2tf(ap[8 * ROWP + 4]);
            }
#pragma unroll
            for (int nt = 0; nt < 4; nt++) {
                const float* bp = Bs + (wn + nt * 8 + lr) * ROWP + kk + lc;
                bf[nt][0] = f2tf(bp[0]);
                bf[nt][1] = f2tf(bp[4]);
            }
#pragma unroll
            for (int mt = 0; mt < 4; mt++)
#pragma unroll
                for (int nt = 0; nt < 4; nt++)
                    mma_tf32(acc[mt][nt], af[mt], bf[nt]);
        }
        __syncthreads();
    }

#pragma unroll
    for (int mt = 0; mt < 4; mt++) {
#pragma unroll
        for (int half = 0; half < 2; half++) {
            const int r = row0 + wm + mt * 16 + lr + half * 8;
            float* crow = C + (size_t)r * HID;
#pragma unroll
            for (int nt = 0; nt < 4; nt++) {
                const int c = col0 + wn + nt * 8 + 2 * lc;
                float2 v;
                v.x = acc[mt][nt][half * 2 + 0] + bias[c];
                v.y = acc[mt][nt][half * 2 + 1] + bias[c + 1];
                if (RND) {
                    v.x = __uint_as_float(f2tf(v.x));
                    v.y = __uint_as_float(f2tf(v.y));
                }
                *(float2*)(crow + c) = v;
            }
        }
    }
}

// ===========================================================================
// Flash attention, tf32 mma.sync.
// 1 CTA = 128 q-rows x 1 head, 8 warps, each warp 16 q-rows end-to-end.
// K-tile = 64 keys, double-buffered cp.async.
// Q,K,V are pre-rounded to tf32 by the projection GEMMs (RND=true).
// ===========================================================================
#define FAQ 128
#define FSK 64
#define KP  132                       // bank = 4*lr + lc : conflict-free
#define VP  136                       // bank = 8*lc + lr : conflict-free
#define KTILE_FLOATS (FSK * KP)       // 8448
#define VTILE_FLOATS (FSK * VP)       // 8704
#define FSTAGE (KTILE_FLOATS + VTILE_FLOATS)
#define FLASH_SMEM_BYTES (2 * FSTAGE * 4)   // 137216

__device__ __forceinline__ void flash_load_kv(
    const float* __restrict__ K, const float* __restrict__ V,
    float* sm, int slot, int kt, int hcol, int tid)
{
    float* Ks = sm + slot * FSTAGE;
    float* Vs = Ks + KTILE_FLOATS;
    const uint32_t ka = smem_u32(Ks);
    const uint32_t va = smem_u32(Vs);
    const int base = kt * FSK;
#pragma unroll
    for (int it = 0; it < 8; it++) {
        const int idx = tid + it * 256;     // 0..2047
        const int row = idx >> 5;
        const int q   = idx & 31;
        cp_async16(ka + (uint32_t)(row * KP + q * 4) * 4u,
                   K + (size_t)(base + row) * HID + hcol + q * 4);
        cp_async16(va + (uint32_t)(row * VP + q * 4) * 4u,
                   V + (size_t)(base + row) * HID + hcol + q * 4);
    }
}

__global__ __launch_bounds__(256, 1) void flash_attn_tf32(
    const float* __restrict__ Q, const float* __restrict__ K,
    const float* __restrict__ V, float* __restrict__ O,
    const float* __restrict__ order_gate, const float* __restrict__ justice_gate)
{
    extern __shared__ float fsm[];

    const int tid  = threadIdx.x;
    const int wid  = tid >> 5;
    const int lane = tid & 31;
    const int lr   = lane >> 2;
    const int lc   = lane & 3;
    const int hcol = blockIdx.y * HD;
    const int qbase = blockIdx.x * FAQ + wid * 16;

    const float sig_j = 1.0f / (1.0f + __expf(-justice_gate[0]));
    const float sig_o = 1.0f / (1.0f + __expf(-order_gate[0]));
    const float alpha = (1.0f - 0.1f * sig_j) * rsqrtf((float)HD);
    const float obias = sig_o * 0.05f / (float)SEQ;

    // Q fragments, register-resident (pre-rounded tf32; f2tf idempotent)
    uint32_t qf[16][4];
    {
        const float* Qb = Q + (size_t)qbase * HID + hcol;
#pragma unroll
        for (int ks = 0; ks < 16; ks++) {
            qf[ks][0] = f2tf(Qb[(size_t)lr * HID + ks * 8 + lc]);
            qf[ks][1] = f2tf(Qb[(size_t)(lr + 8) * HID + ks * 8 + lc]);
            qf[ks][2] = f2tf(Qb[(size_t)lr * HID + ks * 8 + lc + 4]);
            qf[ks][3] = f2tf(Qb[(size_t)(lr + 8) * HID + ks * 8 + lc + 4]);
        }
    }

    float m0 = -1.0e30f, m1 = -1.0e30f, l0 = 0.0f, l1 = 0.0f;
    float of[16][4];
#pragma unroll
    for (int nt = 0; nt < 16; nt++)
#pragma unroll
        for (int i = 0; i < 4; i++) of[nt][i] = 0.0f;

    flash_load_kv(K, V, fsm, 0, 0, hcol, tid);
    CP_COMMIT();

    const int NT = SEQ / FSK;   // 32
    for (int kt = 0; kt < NT; kt++) {
        if (kt + 1 < NT) {
            flash_load_kv(K, V, fsm, (kt + 1) & 1, kt + 1, hcol, tid);
            CP_COMMIT();
            CP_WAIT(1);
        } else {
            CP_WAIT(0);
        }
        __syncthreads();

        const float* Ks = fsm + (kt & 1) * FSTAGE;
        const float* Vs = Ks + KTILE_FLOATS;

        // S = Q K^T   (warp rows x 64 keys)
        float sf[8][4];
#pragma unroll
        for (int nt = 0; nt < 8; nt++)
#pragma unroll
            for (int i = 0; i < 4; i++) sf[nt][i] = 0.0f;

#pragma unroll
        for (int ks = 0; ks < 16; ks++) {
            uint32_t bf[8][2];
#pragma unroll
            for (int nt = 0; nt < 8; nt++) {
                const float* kp_ = Ks + (nt * 8 + lr) * KP + ks * 8 + lc;
                bf[nt][0] = __float_as_uint(kp_[0]);
                bf[nt][1] = __float_as_uint(kp_[4]);
            }
#pragma unroll
            for (int nt = 0; nt < 8; nt++)
                mma_tf32(sf[nt], qf[ks], bf[nt]);
        }

        // scale + key position bias; row max
        float rmax0 = -1.0e30f, rmax1 = -1.0e30f;
#pragma unroll
        for (int nt = 0; nt < 8; nt++) {
            const float col0 = (float)(kt * FSK + nt * 8 + 2 * lc);
            sf[nt][0] = fmaf(sf[nt][0], alpha, obias * col0);
            sf[nt][1] = fmaf(sf[nt][1], alpha, obias * (col0 + 1.0f));
            sf[nt][2] = fmaf(sf[nt][2], alpha, obias * col0);
            sf[nt][3] = fmaf(sf[nt][3], alpha, obias * (col0 + 1.0f));
            rmax0 = fmaxf(rmax0, fmaxf(sf[nt][0], sf[nt][1]));
            rmax1 = fmaxf(rmax1, fmaxf(sf[nt][2], sf[nt][3]));
        }
#pragma unroll
        for (int off = 1; off < 4; off <<= 1) {
            rmax0 = fmaxf(rmax0, __shfl_xor_sync(0xffffffffu, rmax0, off));
            rmax1 = fmaxf(rmax1, __shfl_xor_sync(0xffffffffu, rmax1, off));
        }
        const float m0n = fmaxf(m0, rmax0);
        const float m1n = fmaxf(m1, rmax1);
        const float corr0 = __expf(m0 - m0n);
        const float corr1 = __expf(m1 - m1n);

        // exp + row sums + tf32 P fragments (C-layout)
        float rsum0 = 0.0f, rsum1 = 0.0f;
        uint32_t pf[8][4];
#pragma unroll
        for (int nt = 0; nt < 8; nt++) {
            const float e0 = __expf(sf[nt][0] - m0n);
            const float e1 = __expf(sf[nt][1] - m0n);
            const float e2 = __expf(sf[nt][2] - m1n);
            const float e3 = __expf(sf[nt][3] - m1n);
            rsum0 += e0 + e1;
            rsum1 += e2 + e3;
            pf[nt][0] = f2tf(e0); pf[nt][1] = f2tf(e1);
            pf[nt][2] = f2tf(e2); pf[nt][3] = f2tf(e3);
        }
#pragma unroll
        for (int off = 1; off < 4; off <<= 1) {
            rsum0 += __shfl_xor_sync(0xffffffffu, rsum0, off);
            rsum1 += __shfl_xor_sync(0xffffffffu, rsum1, off);
        }
        l0 = l0 * corr0 + rsum0; m0 = m0n;
        l1 = l1 * corr1 + rsum1; m1 = m1n;

#pragma unroll
        for (int nt = 0; nt < 16; nt++) {
            of[nt][0] *= corr0; of[nt][1] *= corr0;
            of[nt][2] *= corr1; of[nt][3] *= corr1;
        }

        // O += P V : permute P C-layout -> A-layout with quad shuffles
        const int src0 = lr * 4 + (lc >> 1);
        const bool odd = (lc & 1);
#pragma unroll
        for (int kp = 0; kp < 8; kp++) {
            uint32_t pa[4];
            {
                uint32_t v0 = shfl_u32(pf[kp][0], src0);
                uint32_t v1 = shfl_u32(pf[kp][1], src0);
                pa[0] = odd ? v1 : v0;
                uint32_t v2 = shfl_u32(pf[kp][2], src0);
                uint32_t v3 = shfl_u32(pf[kp][3], src0);
                pa[1] = odd ? v3 : v2;
                uint32_t w0 = shfl_u32(pf[kp][0], src0 + 2);
                uint32_t w1 = shfl_u32(pf[kp][1], src0 + 2);
                pa[2] = odd ? w1 : w0;
                uint32_t w2 = shfl_u32(pf[kp][2], src0 + 2);
                uint32_t w3 = shfl_u32(pf[kp][3], src0 + 2);
                pa[3] = odd ? w3 : w2;
            }
#pragma unroll
            for (int nt = 0; nt < 16; nt++) {
                uint32_t bf2[2];
                bf2[0] = __float_as_uint(Vs[(kp * 8 + lc) * VP + nt * 8 + lr]);
                bf2[1] = __float_as_uint(Vs[(kp * 8 + lc + 4) * VP + nt * 8 + lr]);
                mma_tf32(of[nt], pa, bf2);
            }
        }
        __syncthreads();
    }

    // normalize + write
    const float invl0 = 1.0f / l0;
    const float invl1 = 1.0f / l1;
    float* Ob = O + (size_t)qbase * HID + hcol;
#pragma unroll
    for (int nt = 0; nt < 16; nt++) {
        const int c = nt * 8 + 2 * lc;
        float2 v0 = make_float2(of[nt][0] * invl0, of[nt][1] * invl0);
        float2 v1 = make_float2(of[nt][2] * invl1, of[nt][3] * invl1);
        *(float2*)(Ob + (size_t)lr * HID + c) = v0;
        *(float2*)(Ob + (size_t)(lr + 8) * HID + c) = v1;
    }
}

// ===========================================================================
extern "C" void kernel_launch(void* const* d_in, const int* in_sizes, int n_in,
                              void* d_out, int out_size)
{
    const float* X  = (const float*)d_in[0];
    const float* Wq = (const float*)d_in[1];
    const float* bq = (const float*)d_in[2];
    const float* Wk = (const float*)d_in[3];
    const float* bk = (const float*)d_in[4];
    const float* Wv = (const float*)d_in[5];
    const float* bv = (const float*)d_in[6];
    const float* Wo = (const float*)d_in[7];
    const float* bo = (const float*)d_in[8];
    const float* order_gate   = (const float*)d_in[11];
    const float* justice_gate = (const float*)d_in[12];
    float* out = (float*)d_out;

    float *qp, *kp, *vp, *op;
    cudaGetSymbolAddress((void**)&qp, g_Q);
    cudaGetSymbolAddress((void**)&kp, g_K);
    cudaGetSymbolAddress((void**)&vp, g_V);
    cudaGetSymbolAddress((void**)&op, g_O);

    cudaFuncSetAttribute(gemm_tf32_mma<true>,
                         cudaFuncAttributeMaxDynamicSharedMemorySize,
                         GEMM_SMEM_BYTES);
    cudaFuncSetAttribute(gemm_tf32_mma<false>,
                         cudaFuncAttributeMaxDynamicSharedMemorySize,
                         GEMM_SMEM_BYTES);
    cudaFuncSetAttribute(flash_attn_tf32,
                         cudaFuncAttributeMaxDynamicSharedMemorySize,
                         FLASH_SMEM_BYTES);

    dim3 gg(HID / BN, SEQ / BM);   // 16 x 16
    gemm_tf32_mma<true><<<gg, 256, GEMM_SMEM_BYTES>>>(X, Wq, bq, qp);
    gemm_tf32_mma<true><<<gg, 256, GEMM_SMEM_BYTES>>>(X, Wk, bk, kp);
    gemm_tf32_mma<true><<<gg, 256, GEMM_SMEM_BYTES>>>(X, Wv, bv, vp);

    dim3 ga(SEQ / FAQ, NH);        // 16 x 16
    flash_attn_tf32<<<ga, 256, FLASH_SMEM_BYTES>>>(qp, kp, vp, op,
                                                   order_gate, justice_gate);

    gemm_tf32_mma<false><<<gg, 256, GEMM_SMEM_BYTES>>>(op, Wo, bo, out);
}

// round 5
// speedup vs baseline: 3.8810x; 1.0298x over previous
#include <cuda_runtime.h>
#include <math.h>
#include <stdint.h>

#define SEQ   2048
#define HID   2048
#define HD    128
#define NH    16

// Scratch (device globals: allocation-free rule)
__device__ float g_Q[SEQ * HID];
__device__ float g_K[SEQ * HID];
__device__ float g_V[SEQ * HID];
__device__ float g_O[SEQ * HID];
__device__ float g_Xr[SEQ * HID];
__device__ float g_W0[HID * HID];
__device__ float g_W1[HID * HID];
__device__ float g_W2[HID * HID];
__device__ float g_W3[HID * HID];

// ===========================================================================
// Helpers
// ===========================================================================
__device__ __forceinline__ uint32_t smem_u32(const void* p) {
    uint32_t a;
    asm("{ .reg .u64 t; cvta.to.shared.u64 t, %1; cvt.u32.u64 %0, t; }"
        : "=r"(a) : "l"(p));
    return a;
}
__device__ __forceinline__ void cp_async16(uint32_t dst, const void* src) {
    asm volatile("cp.async.cg.shared.global [%0], [%1], 16;" :: "r"(dst), "l"(src));
}
#define CP_COMMIT() asm volatile("cp.async.commit_group;" ::: "memory")
#define CP_WAIT(n)  asm volatile("cp.async.wait_group %0;" :: "n"(n) : "memory")

__device__ __forceinline__ uint32_t f2tf(float x) {
    uint32_t r;
    asm("cvt.rna.tf32.f32 %0, %1;" : "=r"(r) : "f"(x));
    return r;
}
__device__ __forceinline__ uint32_t shfl_u32(uint32_t v, int src) {
    return __shfl_sync(0xffffffffu, v, src);
}

// C[16x8] += A[16x8] * B[8x8]^T   (tf32, fp32 accum)
__device__ __forceinline__ void mma_tf32(float c[4], const uint32_t a[4],
                                         const uint32_t b[2]) {
    asm volatile(
        "mma.sync.aligned.m16n8k8.row.col.f32.tf32.tf32.f32 "
        "{%0,%1,%2,%3}, {%4,%5,%6,%7}, {%8,%9}, {%0,%1,%2,%3};"
        : "+f"(c[0]), "+f"(c[1]), "+f"(c[2]), "+f"(c[3])
        : "r"(a[0]), "r"(a[1]), "r"(a[2]), "r"(a[3]), "r"(b[0]), "r"(b[1]));
}

// ===========================================================================
// Elementwise round-to-nearest tf32 prepass
// ===========================================================================
__global__ __launch_bounds__(256) void round_tf32(const float4* __restrict__ in,
                                                  float4* __restrict__ out, int n4) {
    int i = blockIdx.x * blockDim.x + threadIdx.x;
    if (i >= n4) return;
    float4 v = in[i];
    v.x = __uint_as_float(f2tf(v.x));
    v.y = __uint_as_float(f2tf(v.y));
    v.z = __uint_as_float(f2tf(v.z));
    v.w = __uint_as_float(f2tf(v.w));
    out[i] = v;
}

// ===========================================================================
// tf32 mma.sync GEMM:  C[M,N] = A[M,K] @ B[N,K]^T + bias[N]
// Inputs MUST be pre-rounded to tf32. CTA 128x128, 8 warps (2x4) of 64x32,
// BK=16, 3-stage cp.async, 2 CTAs/SM.
// RND: round output to tf32 (rna) on store.
// ===========================================================================
#define BM 128
#define BN 128
#define BK 16
#define NST 3
#define ROWP 20
#define AT_FLOATS (BM * ROWP)                 // 2560
#define STAGE_FLOATS (2 * AT_FLOATS)          // 5120
#define GEMM_SMEM_BYTES (NST * STAGE_FLOATS * 4)   // 61440

__device__ __forceinline__ void gemm_load_stage(
    const float* __restrict__ Ab, const float* __restrict__ Bb,
    float* sm, int slot, int k0, int tid)
{
    float* As = sm + slot * STAGE_FLOATS;
    float* Bs = As + AT_FLOATS;
    const uint32_t sa = smem_u32(As);
    const uint32_t sb = smem_u32(Bs);
#pragma unroll
    for (int it = 0; it < 2; it++) {
        const int idx = tid + it * 256;       // 0..511
        const int r = idx >> 2;
        const int q = idx & 3;
        const uint32_t off = (uint32_t)(r * ROWP + q * 4) * 4u;
        cp_async16(sa + off, Ab + (size_t)r * HID + k0 + q * 4);
        cp_async16(sb + off, Bb + (size_t)r * HID + k0 + q * 4);
    }
}

template <bool RND>
__global__ __launch_bounds__(256, 2) void gemm_tf32_mma(
    const float* __restrict__ A, const float* __restrict__ B,
    const float* __restrict__ bias, float* __restrict__ C)
{
    extern __shared__ float sm[];

    const int tid  = threadIdx.x;
    const int wid  = tid >> 5;
    const int lane = tid & 31;
    const int lr   = lane >> 2;
    const int lc   = lane & 3;
    const int wm   = (wid >> 2) * 64;
    const int wn   = (wid & 3) * 32;
    const int row0 = blockIdx.y * BM;
    const int col0 = blockIdx.x * BN;

    const float* Ab = A + (size_t)row0 * HID;
    const float* Bb = B + (size_t)col0 * HID;

    float acc[4][4][4];
#pragma unroll
    for (int mt = 0; mt < 4; mt++)
#pragma unroll
        for (int nt = 0; nt < 4; nt++)
#pragma unroll
            for (int i = 0; i < 4; i++) acc[mt][nt][i] = 0.0f;

#pragma unroll
    for (int s = 0; s < NST - 1; s++) {
        gemm_load_stage(Ab, Bb, sm, s, s * BK, tid);
        CP_COMMIT();
    }

    const int KCH = HID / BK;   // 128
    for (int j = 0; j < KCH; j++) {
        if (j + NST - 1 < KCH) {
            gemm_load_stage(Ab, Bb, sm, (j + NST - 1) % NST, (j + NST - 1) * BK, tid);
        }
        CP_COMMIT();
        CP_WAIT(NST - 1);
        __syncthreads();

        const float* As = sm + (j % NST) * STAGE_FLOATS;
        const float* Bs = As + AT_FLOATS;

#pragma unroll
        for (int kk = 0; kk < BK; kk += 8) {
            uint32_t af[4][4], bf[4][2];
#pragma unroll
            for (int mt = 0; mt < 4; mt++) {
                const float* ap = As + (wm + mt * 16 + lr) * ROWP + kk + lc;
                af[mt][0] = __float_as_uint(ap[0]);
                af[mt][1] = __float_as_uint(ap[8 * ROWP]);
                af[mt][2] = __float_as_uint(ap[4]);
                af[mt][3] = __float_as_uint(ap[8 * ROWP + 4]);
            }
#pragma unroll
            for (int nt = 0; nt < 4; nt++) {
                const float* bp = Bs + (wn + nt * 8 + lr) * ROWP + kk + lc;
                bf[nt][0] = __float_as_uint(bp[0]);
                bf[nt][1] = __float_as_uint(bp[4]);
            }
#pragma unroll
            for (int mt = 0; mt < 4; mt++)
#pragma unroll
                for (int nt = 0; nt < 4; nt++)
                    mma_tf32(acc[mt][nt], af[mt], bf[nt]);
        }
        __syncthreads();
    }

#pragma unroll
    for (int mt = 0; mt < 4; mt++) {
#pragma unroll
        for (int half = 0; half < 2; half++) {
            const int r = row0 + wm + mt * 16 + lr + half * 8;
            float* crow = C + (size_t)r * HID;
#pragma unroll
            for (int nt = 0; nt < 4; nt++) {
                const int c = col0 + wn + nt * 8 + 2 * lc;
                float2 v;
                v.x = acc[mt][nt][half * 2 + 0] + bias[c];
                v.y = acc[mt][nt][half * 2 + 1] + bias[c + 1];
                if (RND) {
                    v.x = __uint_as_float(f2tf(v.x));
                    v.y = __uint_as_float(f2tf(v.y));
                }
                *(float2*)(crow + c) = v;
            }
        }
    }
}

// ===========================================================================
// Flash attention, tf32 mma.sync.
// 1 CTA = 128 q-rows x 1 head, 8 warps, each warp 16 q-rows end-to-end.
// K-tile = 64 keys, double-buffered cp.async.
// Q,K,V pre-rounded tf32 (projection RND epilogue). O rounded on store.
// ===========================================================================
#define FAQ 128
#define FSK 64
#define KP  132
#define VP  136
#define KTILE_FLOATS (FSK * KP)
#define VTILE_FLOATS (FSK * VP)
#define FSTAGE (KTILE_FLOATS + VTILE_FLOATS)
#define FLASH_SMEM_BYTES (2 * FSTAGE * 4)   // 137216

__device__ __forceinline__ void flash_load_kv(
    const float* __restrict__ K, const float* __restrict__ V,
    float* sm, int slot, int kt, int hcol, int tid)
{
    float* Ks = sm + slot * FSTAGE;
    float* Vs = Ks + KTILE_FLOATS;
    const uint32_t ka = smem_u32(Ks);
    const uint32_t va = smem_u32(Vs);
    const int base = kt * FSK;
#pragma unroll
    for (int it = 0; it < 8; it++) {
        const int idx = tid + it * 256;
        const int row = idx >> 5;
        const int q   = idx & 31;
        cp_async16(ka + (uint32_t)(row * KP + q * 4) * 4u,
                   K + (size_t)(base + row) * HID + hcol + q * 4);
        cp_async16(va + (uint32_t)(row * VP + q * 4) * 4u,
                   V + (size_t)(base + row) * HID + hcol + q * 4);
    }
}

__global__ __launch_bounds__(256, 1) void flash_attn_tf32(
    const float* __restrict__ Q, const float* __restrict__ K,
    const float* __restrict__ V, float* __restrict__ O,
    const float* __restrict__ order_gate, const float* __restrict__ justice_gate)
{
    extern __shared__ float fsm[];

    const int tid  = threadIdx.x;
    const int wid  = tid >> 5;
    const int lane = tid & 31;
    const int lr   = lane >> 2;
    const int lc   = lane & 3;
    const int hcol = blockIdx.y * HD;
    const int qbase = blockIdx.x * FAQ + wid * 16;

    const float sig_j = 1.0f / (1.0f + __expf(-justice_gate[0]));
    const float sig_o = 1.0f / (1.0f + __expf(-order_gate[0]));
    const float alpha = (1.0f - 0.1f * sig_j) * rsqrtf((float)HD);
    const float obias = sig_o * 0.05f / (float)SEQ;

    uint32_t qf[16][4];
    {
        const float* Qb = Q + (size_t)qbase * HID + hcol;
#pragma unroll
        for (int ks = 0; ks < 16; ks++) {
            qf[ks][0] = __float_as_uint(Qb[(size_t)lr * HID + ks * 8 + lc]);
            qf[ks][1] = __float_as_uint(Qb[(size_t)(lr + 8) * HID + ks * 8 + lc]);
            qf[ks][2] = __float_as_uint(Qb[(size_t)lr * HID + ks * 8 + lc + 4]);
            qf[ks][3] = __float_as_uint(Qb[(size_t)(lr + 8) * HID + ks * 8 + lc + 4]);
        }
    }

    float m0 = -1.0e30f, m1 = -1.0e30f, l0 = 0.0f, l1 = 0.0f;
    float of[16][4];
#pragma unroll
    for (int nt = 0; nt < 16; nt++)
#pragma unroll
        for (int i = 0; i < 4; i++) of[nt][i] = 0.0f;

    flash_load_kv(K, V, fsm, 0, 0, hcol, tid);
    CP_COMMIT();

    const int NT = SEQ / FSK;   // 32
    for (int kt = 0; kt < NT; kt++) {
        if (kt + 1 < NT) {
            flash_load_kv(K, V, fsm, (kt + 1) & 1, kt + 1, hcol, tid);
            CP_COMMIT();
            CP_WAIT(1);
        } else {
            CP_WAIT(0);
        }
        __syncthreads();

        const float* Ks = fsm + (kt & 1) * FSTAGE;
        const float* Vs = Ks + KTILE_FLOATS;

        float sf[8][4];
#pragma unroll
        for (int nt = 0; nt < 8; nt++)
#pragma unroll
            for (int i = 0; i < 4; i++) sf[nt][i] = 0.0f;

#pragma unroll
        for (int ks = 0; ks < 16; ks++) {
            uint32_t bf[8][2];
#pragma unroll
            for (int nt = 0; nt < 8; nt++) {
                const float* kp_ = Ks + (nt * 8 + lr) * KP + ks * 8 + lc;
                bf[nt][0] = __float_as_uint(kp_[0]);
                bf[nt][1] = __float_as_uint(kp_[4]);
            }
#pragma unroll
            for (int nt = 0; nt < 8; nt++)
                mma_tf32(sf[nt], qf[ks], bf[nt]);
        }

        float rmax0 = -1.0e30f, rmax1 = -1.0e30f;
#pragma unroll
        for (int nt = 0; nt < 8; nt++) {
            const float col0 = (float)(kt * FSK + nt * 8 + 2 * lc);
            sf[nt][0] = fmaf(sf[nt][0], alpha, obias * col0);
            sf[nt][1] = fmaf(sf[nt][1], alpha, obias * (col0 + 1.0f));
            sf[nt][2] = fmaf(sf[nt][2], alpha, obias * col0);
            sf[nt][3] = fmaf(sf[nt][3], alpha, obias * (col0 + 1.0f));
            rmax0 = fmaxf(rmax0, fmaxf(sf[nt][0], sf[nt][1]));
            rmax1 = fmaxf(rmax1, fmaxf(sf[nt][2], sf[nt][3]));
        }
#pragma unroll
        for (int off = 1; off < 4; off <<= 1) {
            rmax0 = fmaxf(rmax0, __shfl_xor_sync(0xffffffffu, rmax0, off));
            rmax1 = fmaxf(rmax1, __shfl_xor_sync(0xffffffffu, rmax1, off));
        }
        const float m0n = fmaxf(m0, rmax0);
        const float m1n = fmaxf(m1, rmax1);
        const float corr0 = __expf(m0 - m0n);
        const float corr1 = __expf(m1 - m1n);

        float rsum0 = 0.0f, rsum1 = 0.0f;
        uint32_t pf[8][4];
#pragma unroll
        for (int nt = 0; nt < 8; nt++) {
            const float e0 = __expf(sf[nt][0] - m0n);
            const float e1 = __expf(sf[nt][1] - m0n);
            const float e2 = __expf(sf[nt][2] - m1n);
            const float e3 = __expf(sf[nt][3] - m1n);
            rsum0 += e0 + e1;
            rsum1 += e2 + e3;
            pf[nt][0] = f2tf(e0); pf[nt][1] = f2tf(e1);
            pf[nt][2] = f2tf(e2); pf[nt][3] = f2tf(e3);
        }
#pragma unroll
        for (int off = 1; off < 4; off <<= 1) {
            rsum0 += __shfl_xor_sync(0xffffffffu, rsum0, off);
            rsum1 += __shfl_xor_sync(0xffffffffu, rsum1, off);
        }
        l0 = l0 * corr0 + rsum0; m0 = m0n;
        l1 = l1 * corr1 + rsum1; m1 = m1n;

#pragma unroll
        for (int nt = 0; nt < 16; nt++) {
            of[nt][0] *= corr0; of[nt][1] *= corr0;
            of[nt][2] *= corr1; of[nt][3] *= corr1;
        }

        const int src0 = lr * 4 + (lc >> 1);
        const bool odd = (lc & 1);
#pragma unroll
        for (int kp = 0; kp < 8; kp++) {
            uint32_t pa[4];
            {
                uint32_t v0 = shfl_u32(pf[kp][0], src0);
                uint32_t v1 = shfl_u32(pf[kp][1], src0);
                pa[0] = odd ? v1 : v0;
                uint32_t v2 = shfl_u32(pf[kp][2], src0);
                uint32_t v3 = shfl_u32(pf[kp][3], src0);
                pa[1] = odd ? v3 : v2;
                uint32_t w0 = shfl_u32(pf[kp][0], src0 + 2);
                uint32_t w1 = shfl_u32(pf[kp][1], src0 + 2);
                pa[2] = odd ? w1 : w0;
                uint32_t w2 = shfl_u32(pf[kp][2], src0 + 2);
                uint32_t w3 = shfl_u32(pf[kp][3], src0 + 2);
                pa[3] = odd ? w3 : w2;
            }
#pragma unroll
            for (int nt = 0; nt < 16; nt++) {
                uint32_t bf2[2];
                bf2[0] = __float_as_uint(Vs[(kp * 8 + lc) * VP + nt * 8 + lr]);
                bf2[1] = __float_as_uint(Vs[(kp * 8 + lc + 4) * VP + nt * 8 + lr]);
                mma_tf32(of[nt], pa, bf2);
            }
        }
        __syncthreads();
    }

    // normalize + tf32-round + write (feeds pre-rounded final GEMM)
    const float invl0 = 1.0f / l0;
    const float invl1 = 1.0f / l1;
    float* Ob = O + (size_t)qbase * HID + hcol;
#pragma unroll
    for (int nt = 0; nt < 16; nt++) {
        const int c = nt * 8 + 2 * lc;
        float2 v0, v1;
        v0.x = __uint_as_float(f2tf(of[nt][0] * invl0));
        v0.y = __uint_as_float(f2tf(of[nt][1] * invl0));
        v1.x = __uint_as_float(f2tf(of[nt][2] * invl1));
        v1.y = __uint_as_float(f2tf(of[nt][3] * invl1));
        *(float2*)(Ob + (size_t)lr * HID + c) = v0;
        *(float2*)(Ob + (size_t)(lr + 8) * HID + c) = v1;
    }
}

// ===========================================================================
extern "C" void kernel_launch(void* const* d_in, const int* in_sizes, int n_in,
                              void* d_out, int out_size)
{
    const float* X  = (const float*)d_in[0];
    const float* Wq = (const float*)d_in[1];
    const float* bq = (const float*)d_in[2];
    const float* Wk = (const float*)d_in[3];
    const float* bk = (const float*)d_in[4];
    const float* Wv = (const float*)d_in[5];
    const float* bv = (const float*)d_in[6];
    const float* Wo = (const float*)d_in[7];
    const float* bo = (const float*)d_in[8];
    const float* order_gate   = (const float*)d_in[11];
    const float* justice_gate = (const float*)d_in[12];
    float* out = (float*)d_out;

    float *qp, *kp, *vp, *op, *xr, *w0, *w1, *w2, *w3;
    cudaGetSymbolAddress((void**)&qp, g_Q);
    cudaGetSymbolAddress((void**)&kp, g_K);
    cudaGetSymbolAddress((void**)&vp, g_V);
    cudaGetSymbolAddress((void**)&op, g_O);
    cudaGetSymbolAddress((void**)&xr, g_Xr);
    cudaGetSymbolAddress((void**)&w0, g_W0);
    cudaGetSymbolAddress((void**)&w1, g_W1);
    cudaGetSymbolAddress((void**)&w2, g_W2);
    cudaGetSymbolAddress((void**)&w3, g_W3);

    cudaFuncSetAttribute(gemm_tf32_mma<true>,
                         cudaFuncAttributeMaxDynamicSharedMemorySize,
                         GEMM_SMEM_BYTES);
    cudaFuncSetAttribute(gemm_tf32_mma<false>,
                         cudaFuncAttributeMaxDynamicSharedMemorySize,
                         GEMM_SMEM_BYTES);
    cudaFuncSetAttribute(flash_attn_tf32,
                         cudaFuncAttributeMaxDynamicSharedMemorySize,
                         FLASH_SMEM_BYTES);

    const int N4 = (HID * HID) / 4;
    const dim3 rg((N4 + 255) / 256);

    // prepass: round inputs to tf32 once (hoists CVT out of GEMM hot loops)
    round_tf32<<<rg, 256>>>((const float4*)X,  (float4*)xr, N4);
    round_tf32<<<rg, 256>>>((const float4*)Wq, (float4*)w0, N4);
    round_tf32<<<rg, 256>>>((const float4*)Wk, (float4*)w1, N4);
    round_tf32<<<rg, 256>>>((const float4*)Wv, (float4*)w2, N4);
    round_tf32<<<rg, 256>>>((const float4*)Wo, (float4*)w3, N4);

    dim3 gg(HID / BN, SEQ / BM);   // 16 x 16
    gemm_tf32_mma<true><<<gg, 256, GEMM_SMEM_BYTES>>>(xr, w0, bq, qp);
    gemm_tf32_mma<true><<<gg, 256, GEMM_SMEM_BYTES>>>(xr, w1, bk, kp);
    gemm_tf32_mma<true><<<gg, 256, GEMM_SMEM_BYTES>>>(xr, w2, bv, vp);

    dim3 ga(SEQ / FAQ, NH);        // 16 x 16
    flash_attn_tf32<<<ga, 256, FLASH_SMEM_BYTES>>>(qp, kp, vp, op,
                                                   order_gate, justice_gate);

    gemm_tf32_mma<false><<<gg, 256, GEMM_SMEM_BYTES>>>(op, w3, bo, out);
}

// round 6
// speedup vs baseline: 4.1498x; 1.0693x over previous
#include <cuda_runtime.h>
#include <math.h>
#include <stdint.h>

#define SEQ   2048
#define HID   2048
#define HD    128
#define NH    16

// Scratch (device globals: allocation-free rule)
__device__ float g_Q[SEQ * HID];
__device__ float g_K[SEQ * HID];
__device__ float g_V[SEQ * HID];
__device__ float g_O[SEQ * HID];
__device__ float g_Xr[SEQ * HID];
__device__ float g_W0[HID * HID];
__device__ float g_W1[HID * HID];
__device__ float g_W2[HID * HID];
__device__ float g_W3[HID * HID];

// ===========================================================================
// Helpers
// ===========================================================================
__device__ __forceinline__ uint32_t smem_u32(const void* p) {
    uint32_t a;
    asm("{ .reg .u64 t; cvta.to.shared.u64 t, %1; cvt.u32.u64 %0, t; }"
        : "=r"(a) : "l"(p));
    return a;
}
__device__ __forceinline__ void cp_async16(uint32_t dst, const void* src) {
    asm volatile("cp.async.cg.shared.global [%0], [%1], 16;" :: "r"(dst), "l"(src));
}
#define CP_COMMIT() asm volatile("cp.async.commit_group;" ::: "memory")
#define CP_WAIT(n)  asm volatile("cp.async.wait_group %0;" :: "n"(n) : "memory")

__device__ __forceinline__ uint32_t f2tf(float x) {
    uint32_t r;
    asm("cvt.rna.tf32.f32 %0, %1;" : "=r"(r) : "f"(x));
    return r;
}
__device__ __forceinline__ uint32_t shfl_u32(uint32_t v, int src) {
    return __shfl_sync(0xffffffffu, v, src);
}

// ldmatrix x4 (b16 view; moves 4x (8 rows x 16B) — tf32 fragment trick)
__device__ __forceinline__ void ldsm_x4(uint32_t r[4], uint32_t addr) {
    asm volatile("ldmatrix.sync.aligned.m8n8.x4.shared.b16 {%0,%1,%2,%3}, [%4];"
        : "=r"(r[0]), "=r"(r[1]), "=r"(r[2]), "=r"(r[3]) : "r"(addr));
}

// C[16x8] += A[16x8] * B[8x8]^T   (tf32, fp32 accum)
__device__ __forceinline__ void mma_tf32(float c[4], const uint32_t a[4],
                                         const uint32_t b[2]) {
    asm volatile(
        "mma.sync.aligned.m16n8k8.row.col.f32.tf32.tf32.f32 "
        "{%0,%1,%2,%3}, {%4,%5,%6,%7}, {%8,%9}, {%0,%1,%2,%3};"
        : "+f"(c[0]), "+f"(c[1]), "+f"(c[2]), "+f"(c[3])
        : "r"(a[0]), "r"(a[1]), "r"(a[2]), "r"(a[3]), "r"(b[0]), "r"(b[1]));
}

// ===========================================================================
// Elementwise round-to-nearest tf32 prepass
// ===========================================================================
__global__ __launch_bounds__(256) void round_tf32(const float4* __restrict__ in,
                                                  float4* __restrict__ out, int n4) {
    int i = blockIdx.x * blockDim.x + threadIdx.x;
    if (i >= n4) return;
    float4 v = in[i];
    v.x = __uint_as_float(f2tf(v.x));
    v.y = __uint_as_float(f2tf(v.y));
    v.z = __uint_as_float(f2tf(v.z));
    v.w = __uint_as_float(f2tf(v.w));
    out[i] = v;
}

// ===========================================================================
// tf32 mma.sync GEMM:  C[M,N] = A[M,K] @ B[N,K]^T + bias[N]
// Inputs MUST be pre-rounded to tf32. CTA 128x128, 8 warps (2x4) of 64x32,
// BK=32, 2-stage cp.async double buffer, ldmatrix.x4 fragment loads,
// 2 CTAs/SM.  RND: round output to tf32 (rna) on store.
// ===========================================================================
#define BM 128
#define BN 128
#define BK 32
#define ROWP 36
#define AT_FLOATS (BM * ROWP)                 // 4608
#define STAGE_FLOATS (2 * AT_FLOATS)          // 9216
#define GEMM_SMEM_BYTES (2 * STAGE_FLOATS * 4)   // 73728

__device__ __forceinline__ void gemm_load_stage(
    const float* __restrict__ Ab, const float* __restrict__ Bb,
    float* sm, int slot, int k0, int tid)
{
    float* As = sm + slot * STAGE_FLOATS;
    float* Bs = As + AT_FLOATS;
    const uint32_t sa = smem_u32(As);
    const uint32_t sb = smem_u32(Bs);
#pragma unroll
    for (int it = 0; it < 4; it++) {
        const int idx = tid + it * 256;       // 0..1023
        const int r = idx >> 3;
        const int q = idx & 7;
        const uint32_t off = (uint32_t)(r * ROWP + q * 4) * 4u;
        cp_async16(sa + off, Ab + (size_t)r * HID + k0 + q * 4);
        cp_async16(sb + off, Bb + (size_t)r * HID + k0 + q * 4);
    }
}

template <bool RND>
__global__ __launch_bounds__(256, 2) void gemm_tf32_mma(
    const float* __restrict__ A, const float* __restrict__ B,
    const float* __restrict__ bias, float* __restrict__ C)
{
    extern __shared__ float sm[];

    const int tid  = threadIdx.x;
    const int wid  = tid >> 5;
    const int lane = tid & 31;
    const int lr   = lane >> 2;
    const int lc   = lane & 3;
    const int l15  = lane & 15;              // ldmatrix row within 16-row group
    const int lcol = (lane >> 4) << 2;       // ldmatrix k-offset (0 or 4)
    const int wm   = (wid >> 2) * 64;
    const int wn   = (wid & 3) * 32;
    const int row0 = blockIdx.y * BM;
    const int col0 = blockIdx.x * BN;

    const float* Ab = A + (size_t)row0 * HID;
    const float* Bb = B + (size_t)col0 * HID;

    float acc[4][4][4];
#pragma unroll
    for (int mt = 0; mt < 4; mt++)
#pragma unroll
        for (int nt = 0; nt < 4; nt++)
#pragma unroll
            for (int i = 0; i < 4; i++) acc[mt][nt][i] = 0.0f;

    // prologue: fill stage 0
    gemm_load_stage(Ab, Bb, sm, 0, 0, tid);
    CP_COMMIT();

    const uint32_t sbase = smem_u32(sm);
    const int KCH = HID / BK;   // 64
    for (int j = 0; j < KCH; j++) {
        __syncthreads();     // all warps done with buffer (j+1)&1 from chunk j-1
        if (j + 1 < KCH) {
            gemm_load_stage(Ab, Bb, sm, (j + 1) & 1, (j + 1) * BK, tid);
            CP_COMMIT();
            CP_WAIT(1);      // chunk j resident, chunk j+1 in flight
        } else {
            CP_WAIT(0);
        }
        __syncthreads();

        const uint32_t sa = sbase + (uint32_t)((j & 1) * STAGE_FLOATS) * 4u;
        const uint32_t sb = sa + AT_FLOATS * 4u;

#pragma unroll
        for (int kk = 0; kk < BK; kk += 8) {
            uint32_t af[4][4], bf[4][2];
#pragma unroll
            for (int mt = 0; mt < 4; mt++)
                ldsm_x4(af[mt],
                        sa + (uint32_t)((wm + mt * 16 + l15) * ROWP + kk + lcol) * 4u);
#pragma unroll
            for (int np = 0; np < 2; np++) {
                uint32_t t[4];
                ldsm_x4(t,
                        sb + (uint32_t)((wn + np * 16 + l15) * ROWP + kk + lcol) * 4u);
                bf[2 * np + 0][0] = t[0];
                bf[2 * np + 1][0] = t[1];
                bf[2 * np + 0][1] = t[2];
                bf[2 * np + 1][1] = t[3];
            }
#pragma unroll
            for (int mt = 0; mt < 4; mt++)
#pragma unroll
                for (int nt = 0; nt < 4; nt++)
                    mma_tf32(acc[mt][nt], af[mt], bf[nt]);
        }
    }

#pragma unroll
    for (int mt = 0; mt < 4; mt++) {
#pragma unroll
        for (int half = 0; half < 2; half++) {
            const int r = row0 + wm + mt * 16 + lr + half * 8;
            float* crow = C + (size_t)r * HID;
#pragma unroll
            for (int nt = 0; nt < 4; nt++) {
                const int c = col0 + wn + nt * 8 + 2 * lc;
                float2 v;
                v.x = acc[mt][nt][half * 2 + 0] + bias[c];
                v.y = acc[mt][nt][half * 2 + 1] + bias[c + 1];
                if (RND) {
                    v.x = __uint_as_float(f2tf(v.x));
                    v.y = __uint_as_float(f2tf(v.y));
                }
                *(float2*)(crow + c) = v;
            }
        }
    }
}

// ===========================================================================
// Flash attention, tf32 mma.sync (unchanged from round 5 — known good).
// ===========================================================================
#define FAQ 128
#define FSK 64
#define KP  132
#define VP  136
#define KTILE_FLOATS (FSK * KP)
#define VTILE_FLOATS (FSK * VP)
#define FSTAGE (KTILE_FLOATS + VTILE_FLOATS)
#define FLASH_SMEM_BYTES (2 * FSTAGE * 4)   // 137216

__device__ __forceinline__ void flash_load_kv(
    const float* __restrict__ K, const float* __restrict__ V,
    float* sm, int slot, int kt, int hcol, int tid)
{
    float* Ks = sm + slot * FSTAGE;
    float* Vs = Ks + KTILE_FLOATS;
    const uint32_t ka = smem_u32(Ks);
    const uint32_t va = smem_u32(Vs);
    const int base = kt * FSK;
#pragma unroll
    for (int it = 0; it < 8; it++) {
        const int idx = tid + it * 256;
        const int row = idx >> 5;
        const int q   = idx & 31;
        cp_async16(ka + (uint32_t)(row * KP + q * 4) * 4u,
                   K + (size_t)(base + row) * HID + hcol + q * 4);
        cp_async16(va + (uint32_t)(row * VP + q * 4) * 4u,
                   V + (size_t)(base + row) * HID + hcol + q * 4);
    }
}

__global__ __launch_bounds__(256, 1) void flash_attn_tf32(
    const float* __restrict__ Q, const float* __restrict__ K,
    const float* __restrict__ V, float* __restrict__ O,
    const float* __restrict__ order_gate, const float* __restrict__ justice_gate)
{
    extern __shared__ float fsm[];

    const int tid  = threadIdx.x;
    const int wid  = tid >> 5;
    const int lane = tid & 31;
    const int lr   = lane >> 2;
    const int lc   = lane & 3;
    const int hcol = blockIdx.y * HD;
    const int qbase = blockIdx.x * FAQ + wid * 16;

    const float sig_j = 1.0f / (1.0f + __expf(-justice_gate[0]));
    const float sig_o = 1.0f / (1.0f + __expf(-order_gate[0]));
    const float alpha = (1.0f - 0.1f * sig_j) * rsqrtf((float)HD);
    const float obias = sig_o * 0.05f / (float)SEQ;

    uint32_t qf[16][4];
    {
        const float* Qb = Q + (size_t)qbase * HID + hcol;
#pragma unroll
        for (int ks = 0; ks < 16; ks++) {
            qf[ks][0] = __float_as_uint(Qb[(size_t)lr * HID + ks * 8 + lc]);
            qf[ks][1] = __float_as_uint(Qb[(size_t)(lr + 8) * HID + ks * 8 + lc]);
            qf[ks][2] = __float_as_uint(Qb[(size_t)lr * HID + ks * 8 + lc + 4]);
            qf[ks][3] = __float_as_uint(Qb[(size_t)(lr + 8) * HID + ks * 8 + lc + 4]);
        }
    }

    float m0 = -1.0e30f, m1 = -1.0e30f, l0 = 0.0f, l1 = 0.0f;
    float of[16][4];
#pragma unroll
    for (int nt = 0; nt < 16; nt++)
#pragma unroll
        for (int i = 0; i < 4; i++) of[nt][i] = 0.0f;

    flash_load_kv(K, V, fsm, 0, 0, hcol, tid);
    CP_COMMIT();

    const int NT = SEQ / FSK;   // 32
    for (int kt = 0; kt < NT; kt++) {
        if (kt + 1 < NT) {
            flash_load_kv(K, V, fsm, (kt + 1) & 1, kt + 1, hcol, tid);
            CP_COMMIT();
            CP_WAIT(1);
        } else {
            CP_WAIT(0);
        }
        __syncthreads();

        const float* Ks = fsm + (kt & 1) * FSTAGE;
        const float* Vs = Ks + KTILE_FLOATS;

        float sf[8][4];
#pragma unroll
        for (int nt = 0; nt < 8; nt++)
#pragma unroll
            for (int i = 0; i < 4; i++) sf[nt][i] = 0.0f;

#pragma unroll
        for (int ks = 0; ks < 16; ks++) {
            uint32_t bf[8][2];
#pragma unroll
            for (int nt = 0; nt < 8; nt++) {
                const float* kp_ = Ks + (nt * 8 + lr) * KP + ks * 8 + lc;
                bf[nt][0] = __float_as_uint(kp_[0]);
                bf[nt][1] = __float_as_uint(kp_[4]);
            }
#pragma unroll
            for (int nt = 0; nt < 8; nt++)
                mma_tf32(sf[nt], qf[ks], bf[nt]);
        }

        float rmax0 = -1.0e30f, rmax1 = -1.0e30f;
#pragma unroll
        for (int nt = 0; nt < 8; nt++) {
            const float col0 = (float)(kt * FSK + nt * 8 + 2 * lc);
            sf[nt][0] = fmaf(sf[nt][0], alpha, obias * col0);
            sf[nt][1] = fmaf(sf[nt][1], alpha, obias * (col0 + 1.0f));
            sf[nt][2] = fmaf(sf[nt][2], alpha, obias * col0);
            sf[nt][3] = fmaf(sf[nt][3], alpha, obias * (col0 + 1.0f));
            rmax0 = fmaxf(rmax0, fmaxf(sf[nt][0], sf[nt][1]));
            rmax1 = fmaxf(rmax1, fmaxf(sf[nt][2], sf[nt][3]));
        }
#pragma unroll
        for (int off = 1; off < 4; off <<= 1) {
            rmax0 = fmaxf(rmax0, __shfl_xor_sync(0xffffffffu, rmax0, off));
            rmax1 = fmaxf(rmax1, __shfl_xor_sync(0xffffffffu, rmax1, off));
        }
        const float m0n = fmaxf(m0, rmax0);
        const float m1n = fmaxf(m1, rmax1);
        const float corr0 = __expf(m0 - m0n);
        const float corr1 = __expf(m1 - m1n);

        float rsum0 = 0.0f, rsum1 = 0.0f;
        uint32_t pf[8][4];
#pragma unroll
        for (int nt = 0; nt < 8; nt++) {
            const float e0 = __expf(sf[nt][0] - m0n);
            const float e1 = __expf(sf[nt][1] - m0n);
            const float e2 = __expf(sf[nt][2] - m1n);
            const float e3 = __expf(sf[nt][3] - m1n);
            rsum0 += e0 + e1;
            rsum1 += e2 + e3;
            pf[nt][0] = f2tf(e0); pf[nt][1] = f2tf(e1);
            pf[nt][2] = f2tf(e2); pf[nt][3] = f2tf(e3);
        }
#pragma unroll
        for (int off = 1; off < 4; off <<= 1) {
            rsum0 += __shfl_xor_sync(0xffffffffu, rsum0, off);
            rsum1 += __shfl_xor_sync(0xffffffffu, rsum1, off);
        }
        l0 = l0 * corr0 + rsum0; m0 = m0n;
        l1 = l1 * corr1 + rsum1; m1 = m1n;

#pragma unroll
        for (int nt = 0; nt < 16; nt++) {
            of[nt][0] *= corr0; of[nt][1] *= corr0;
            of[nt][2] *= corr1; of[nt][3] *= corr1;
        }

        const int src0 = lr * 4 + (lc >> 1);
        const bool odd = (lc & 1);
#pragma unroll
        for (int kp = 0; kp < 8; kp++) {
            uint32_t pa[4];
            {
                uint32_t v0 = shfl_u32(pf[kp][0], src0);
                uint32_t v1 = shfl_u32(pf[kp][1], src0);
                pa[0] = odd ? v1 : v0;
                uint32_t v2 = shfl_u32(pf[kp][2], src0);
                uint32_t v3 = shfl_u32(pf[kp][3], src0);
                pa[1] = odd ? v3 : v2;
                uint32_t w0 = shfl_u32(pf[kp][0], src0 + 2);
                uint32_t w1 = shfl_u32(pf[kp][1], src0 + 2);
                pa[2] = odd ? w1 : w0;
                uint32_t w2 = shfl_u32(pf[kp][2], src0 + 2);
                uint32_t w3 = shfl_u32(pf[kp][3], src0 + 2);
                pa[3] = odd ? w3 : w2;
            }
#pragma unroll
            for (int nt = 0; nt < 16; nt++) {
                uint32_t bf2[2];
                bf2[0] = __float_as_uint(Vs[(kp * 8 + lc) * VP + nt * 8 + lr]);
                bf2[1] = __float_as_uint(Vs[(kp * 8 + lc + 4) * VP + nt * 8 + lr]);
                mma_tf32(of[nt], pa, bf2);
            }
        }
        __syncthreads();
    }

    const float invl0 = 1.0f / l0;
    const float invl1 = 1.0f / l1;
    float* Ob = O + (size_t)qbase * HID + hcol;
#pragma unroll
    for (int nt = 0; nt < 16; nt++) {
        const int c = nt * 8 + 2 * lc;
        float2 v0, v1;
        v0.x = __uint_as_float(f2tf(of[nt][0] * invl0));
        v0.y = __uint_as_float(f2tf(of[nt][1] * invl0));
        v1.x = __uint_as_float(f2tf(of[nt][2] * invl1));
        v1.y = __uint_as_float(f2tf(of[nt][3] * invl1));
        *(float2*)(Ob + (size_t)lr * HID + c) = v0;
        *(float2*)(Ob + (size_t)(lr + 8) * HID + c) = v1;
    }
}

// ===========================================================================
extern "C" void kernel_launch(void* const* d_in, const int* in_sizes, int n_in,
                              void* d_out, int out_size)
{
    const float* X  = (const float*)d_in[0];
    const float* Wq = (const float*)d_in[1];
    const float* bq = (const float*)d_in[2];
    const float* Wk = (const float*)d_in[3];
    const float* bk = (const float*)d_in[4];
    const float* Wv = (const float*)d_in[5];
    const float* bv = (const float*)d_in[6];
    const float* Wo = (const float*)d_in[7];
    const float* bo = (const float*)d_in[8];
    const float* order_gate   = (const float*)d_in[11];
    const float* justice_gate = (const float*)d_in[12];
    float* out = (float*)d_out;

    float *qp, *kp, *vp, *op, *xr, *w0, *w1, *w2, *w3;
    cudaGetSymbolAddress((void**)&qp, g_Q);
    cudaGetSymbolAddress((void**)&kp, g_K);
    cudaGetSymbolAddress((void**)&vp, g_V);
    cudaGetSymbolAddress((void**)&op, g_O);
    cudaGetSymbolAddress((void**)&xr, g_Xr);
    cudaGetSymbolAddress((void**)&w0, g_W0);
    cudaGetSymbolAddress((void**)&w1, g_W1);
    cudaGetSymbolAddress((void**)&w2, g_W2);
    cudaGetSymbolAddress((void**)&w3, g_W3);

    cudaFuncSetAttribute(gemm_tf32_mma<true>,
                         cudaFuncAttributeMaxDynamicSharedMemorySize,
                         GEMM_SMEM_BYTES);
    cudaFuncSetAttribute(gemm_tf32_mma<false>,
                         cudaFuncAttributeMaxDynamicSharedMemorySize,
                         GEMM_SMEM_BYTES);
    cudaFuncSetAttribute(flash_attn_tf32,
                         cudaFuncAttributeMaxDynamicSharedMemorySize,
                         FLASH_SMEM_BYTES);

    const int N4 = (HID * HID) / 4;
    const dim3 rg((N4 + 255) / 256);

    // prepass: round inputs to tf32 once
    round_tf32<<<rg, 256>>>((const float4*)X,  (float4*)xr, N4);
    round_tf32<<<rg, 256>>>((const float4*)Wq, (float4*)w0, N4);
    round_tf32<<<rg, 256>>>((const float4*)Wk, (float4*)w1, N4);
    round_tf32<<<rg, 256>>>((const float4*)Wv, (float4*)w2, N4);
    round_tf32<<<rg, 256>>>((const float4*)Wo, (float4*)w3, N4);

    dim3 gg(HID / BN, SEQ / BM);   // 16 x 16
    gemm_tf32_mma<true><<<gg, 256, GEMM_SMEM_BYTES>>>(xr, w0, bq, qp);
    gemm_tf32_mma<true><<<gg, 256, GEMM_SMEM_BYTES>>>(xr, w1, bk, kp);
    gemm_tf32_mma<true><<<gg, 256, GEMM_SMEM_BYTES>>>(xr, w2, bv, vp);

    dim3 ga(SEQ / FAQ, NH);        // 16 x 16
    flash_attn_tf32<<<ga, 256, FLASH_SMEM_BYTES>>>(qp, kp, vp, op,
                                                   order_gate, justice_gate);

    gemm_tf32_mma<false><<<gg, 256, GEMM_SMEM_BYTES>>>(op, w3, bo, out);
}

// round 7
// speedup vs baseline: 4.1980x; 1.0116x over previous
#include <cuda_runtime.h>
#include <math.h>
#include <stdint.h>

#define SEQ   2048
#define HID   2048
#define HD    128
#define NH    16

// Scratch (device globals: allocation-free rule)
__device__ float g_Q[SEQ * HID];
__device__ float g_K[SEQ * HID];
__device__ float g_V[SEQ * HID];
__device__ float g_O[SEQ * HID];
__device__ float g_Xr[SEQ * HID];
__device__ float g_W0[HID * HID];
__device__ float g_W1[HID * HID];
__device__ float g_W2[HID * HID];
__device__ float g_W3[HID * HID];

// ===========================================================================
// Helpers
// ===========================================================================
__device__ __forceinline__ uint32_t smem_u32(const void* p) {
    uint32_t a;
    asm("{ .reg .u64 t; cvta.to.shared.u64 t, %1; cvt.u32.u64 %0, t; }"
        : "=r"(a) : "l"(p));
    return a;
}
__device__ __forceinline__ void cp_async16(uint32_t dst, const void* src) {
    asm volatile("cp.async.cg.shared.global [%0], [%1], 16;" :: "r"(dst), "l"(src));
}
#define CP_COMMIT() asm volatile("cp.async.commit_group;" ::: "memory")
#define CP_WAIT(n)  asm volatile("cp.async.wait_group %0;" :: "n"(n) : "memory")

__device__ __forceinline__ uint32_t f2tf(float x) {
    uint32_t r;
    asm("cvt.rna.tf32.f32 %0, %1;" : "=r"(r) : "f"(x));
    return r;
}
__device__ __forceinline__ uint32_t shfl_u32(uint32_t v, int src) {
    return __shfl_sync(0xffffffffu, v, src);
}

// ldmatrix x4 (b16 view; moves 4x (8 rows x 16B) — tf32 fragment trick)
__device__ __forceinline__ void ldsm_x4(uint32_t r[4], uint32_t addr) {
    asm volatile("ldmatrix.sync.aligned.m8n8.x4.shared.b16 {%0,%1,%2,%3}, [%4];"
        : "=r"(r[0]), "=r"(r[1]), "=r"(r[2]), "=r"(r[3]) : "r"(addr));
}

// C[16x8] += A[16x8] * B[8x8]^T   (tf32, fp32 accum)
__device__ __forceinline__ void mma_tf32(float c[4], const uint32_t a[4],
                                         const uint32_t b[2]) {
    asm volatile(
        "mma.sync.aligned.m16n8k8.row.col.f32.tf32.tf32.f32 "
        "{%0,%1,%2,%3}, {%4,%5,%6,%7}, {%8,%9}, {%0,%1,%2,%3};"
        : "+f"(c[0]), "+f"(c[1]), "+f"(c[2]), "+f"(c[3])
        : "r"(a[0]), "r"(a[1]), "r"(a[2]), "r"(a[3]), "r"(b[0]), "r"(b[1]));
}

// ===========================================================================
// Elementwise round-to-nearest tf32 prepass
// ===========================================================================
__global__ __launch_bounds__(256) void round_tf32(const float4* __restrict__ in,
                                                  float4* __restrict__ out, int n4) {
    int i = blockIdx.x * blockDim.x + threadIdx.x;
    if (i >= n4) return;
    float4 v = in[i];
    v.x = __uint_as_float(f2tf(v.x));
    v.y = __uint_as_float(f2tf(v.y));
    v.z = __uint_as_float(f2tf(v.z));
    v.w = __uint_as_float(f2tf(v.w));
    out[i] = v;
}

// ===========================================================================
// tf32 mma.sync GEMM core:  C[M,N] = A[M,K] @ B[N,K]^T + bias[N]
// CTA 128x128, 8 warps (2x4) of 64x32, BK=32, 3-stage cp.async,
// ldmatrix.x4 fragment loads, 2 CTAs/SM.
// ===========================================================================
#define BM 128
#define BN 128
#define BK 32
#define NST 3
#define ROWP 36
#define AT_FLOATS (BM * ROWP)                 // 4608
#define STAGE_FLOATS (2 * AT_FLOATS)          // 9216
#define GEMM_SMEM_BYTES (NST * STAGE_FLOATS * 4)   // 110592

__device__ __forceinline__ void gemm_load_stage(
    const float* __restrict__ Ab, const float* __restrict__ Bb,
    float* sm, int slot, int k0, int tid)
{
    float* As = sm + slot * STAGE_FLOATS;
    float* Bs = As + AT_FLOATS;
    const uint32_t sa = smem_u32(As);
    const uint32_t sb = smem_u32(Bs);
#pragma unroll
    for (int it = 0; it < 4; it++) {
        const int idx = tid + it * 256;       // 0..1023
        const int r = idx >> 3;
        const int q = idx & 7;
        const uint32_t off = (uint32_t)(r * ROWP + q * 4) * 4u;
        cp_async16(sa + off, Ab + (size_t)r * HID + k0 + q * 4);
        cp_async16(sb + off, Bb + (size_t)r * HID + k0 + q * 4);
    }
}

template <bool RND>
__device__ __forceinline__ void gemm_body(
    const float* __restrict__ A, const float* __restrict__ B,
    const float* __restrict__ bias, float* __restrict__ C,
    float* sm, int row0, int col0)
{
    const int tid  = threadIdx.x;
    const int wid  = tid >> 5;
    const int lane = tid & 31;
    const int lr   = lane >> 2;
    const int lc   = lane & 3;
    const int l15  = lane & 15;
    const int lcol = (lane >> 4) << 2;
    const int wm   = (wid >> 2) * 64;
    const int wn   = (wid & 3) * 32;

    const float* Ab = A + (size_t)row0 * HID;
    const float* Bb = B + (size_t)col0 * HID;

    float acc[4][4][4];
#pragma unroll
    for (int mt = 0; mt < 4; mt++)
#pragma unroll
        for (int nt = 0; nt < 4; nt++)
#pragma unroll
            for (int i = 0; i < 4; i++) acc[mt][nt][i] = 0.0f;

#pragma unroll
    for (int s = 0; s < NST - 1; s++) {
        gemm_load_stage(Ab, Bb, sm, s, s * BK, tid);
        CP_COMMIT();
    }

    const uint32_t sbase = smem_u32(sm);
    const int KCH = HID / BK;   // 64
    for (int j = 0; j < KCH; j++) {
        if (j + NST - 1 < KCH) {
            gemm_load_stage(Ab, Bb, sm, (j + NST - 1) % NST, (j + NST - 1) * BK, tid);
        }
        CP_COMMIT();
        CP_WAIT(NST - 1);
        __syncthreads();

        const uint32_t sa = sbase + (uint32_t)((j % NST) * STAGE_FLOATS) * 4u;
        const uint32_t sb = sa + AT_FLOATS * 4u;

#pragma unroll
        for (int kk = 0; kk < BK; kk += 8) {
            uint32_t af[4][4], bf[4][2];
#pragma unroll
            for (int mt = 0; mt < 4; mt++)
                ldsm_x4(af[mt],
                        sa + (uint32_t)((wm + mt * 16 + l15) * ROWP + kk + lcol) * 4u);
#pragma unroll
            for (int np = 0; np < 2; np++) {
                uint32_t t[4];
                ldsm_x4(t,
                        sb + (uint32_t)((wn + np * 16 + l15) * ROWP + kk + lcol) * 4u);
                bf[2 * np + 0][0] = t[0];
                bf[2 * np + 1][0] = t[1];
                bf[2 * np + 0][1] = t[2];
                bf[2 * np + 1][1] = t[3];
            }
#pragma unroll
            for (int mt = 0; mt < 4; mt++)
#pragma unroll
                for (int nt = 0; nt < 4; nt++)
                    mma_tf32(acc[mt][nt], af[mt], bf[nt]);
        }
        __syncthreads();
    }

#pragma unroll
    for (int mt = 0; mt < 4; mt++) {
#pragma unroll
        for (int half = 0; half < 2; half++) {
            const int r = row0 + wm + mt * 16 + lr + half * 8;
            float* crow = C + (size_t)r * HID;
#pragma unroll
            for (int nt = 0; nt < 4; nt++) {
                const int c = col0 + wn + nt * 8 + 2 * lc;
                float2 v;
                v.x = acc[mt][nt][half * 2 + 0] + bias[c];
                v.y = acc[mt][nt][half * 2 + 1] + bias[c + 1];
                if (RND) {
                    v.x = __uint_as_float(f2tf(v.x));
                    v.y = __uint_as_float(f2tf(v.y));
                }
                *(float2*)(crow + c) = v;
            }
        }
    }
}

// Fused QKV projection: blockIdx.z selects weight/bias/output.
__global__ __launch_bounds__(256, 2) void gemm_qkv(
    const float* __restrict__ A,
    const float* __restrict__ W0, const float* __restrict__ W1,
    const float* __restrict__ W2,
    const float* __restrict__ b0, const float* __restrict__ b1,
    const float* __restrict__ b2,
    float* __restrict__ C0, float* __restrict__ C1, float* __restrict__ C2)
{
    extern __shared__ float sm[];
    const int z = blockIdx.z;
    const float* B    = (z == 0) ? W0 : (z == 1) ? W1 : W2;
    const float* bias = (z == 0) ? b0 : (z == 1) ? b1 : b2;
    float* C          = (z == 0) ? C0 : (z == 1) ? C1 : C2;
    gemm_body<true>(A, B, bias, C, sm, blockIdx.y * BM, blockIdx.x * BN);
}

// Single GEMM (output projection)
__global__ __launch_bounds__(256, 2) void gemm_single(
    const float* __restrict__ A, const float* __restrict__ B,
    const float* __restrict__ bias, float* __restrict__ C)
{
    extern __shared__ float sm[];
    gemm_body<false>(A, B, bias, C, sm, blockIdx.y * BM, blockIdx.x * BN);
}

// ===========================================================================
// Flash attention, tf32 mma.sync. K fragments via ldmatrix.x4.
// 1 CTA = 128 q-rows x 1 head, 8 warps, each warp 16 q-rows end-to-end.
// ===========================================================================
#define FAQ 128
#define FSK 64
#define KP  132
#define VP  136
#define KTILE_FLOATS (FSK * KP)
#define VTILE_FLOATS (FSK * VP)
#define FSTAGE (KTILE_FLOATS + VTILE_FLOATS)
#define FLASH_SMEM_BYTES (2 * FSTAGE * 4)   // 137216

__device__ __forceinline__ void flash_load_kv(
    const float* __restrict__ K, const float* __restrict__ V,
    float* sm, int slot, int kt, int hcol, int tid)
{
    float* Ks = sm + slot * FSTAGE;
    float* Vs = Ks + KTILE_FLOATS;
    const uint32_t ka = smem_u32(Ks);
    const uint32_t va = smem_u32(Vs);
    const int base = kt * FSK;
#pragma unroll
    for (int it = 0; it < 8; it++) {
        const int idx = tid + it * 256;
        const int row = idx >> 5;
        const int q   = idx & 31;
        cp_async16(ka + (uint32_t)(row * KP + q * 4) * 4u,
                   K + (size_t)(base + row) * HID + hcol + q * 4);
        cp_async16(va + (uint32_t)(row * VP + q * 4) * 4u,
                   V + (size_t)(base + row) * HID + hcol + q * 4);
    }
}

__global__ __launch_bounds__(256, 1) void flash_attn_tf32(
    const float* __restrict__ Q, const float* __restrict__ K,
    const float* __restrict__ V, float* __restrict__ O,
    const float* __restrict__ order_gate, const float* __restrict__ justice_gate)
{
    extern __shared__ float fsm[];

    const int tid  = threadIdx.x;
    const int wid  = tid >> 5;
    const int lane = tid & 31;
    const int lr   = lane >> 2;
    const int lc   = lane & 3;
    const int l15  = lane & 15;
    const int lcol = (lane >> 4) << 2;
    const int hcol = blockIdx.y * HD;
    const int qbase = blockIdx.x * FAQ + wid * 16;

    const float sig_j = 1.0f / (1.0f + __expf(-justice_gate[0]));
    const float sig_o = 1.0f / (1.0f + __expf(-order_gate[0]));
    const float alpha = (1.0f - 0.1f * sig_j) * rsqrtf((float)HD);
    const float obias = sig_o * 0.05f / (float)SEQ;

    uint32_t qf[16][4];
    {
        const float* Qb = Q + (size_t)qbase * HID + hcol;
#pragma unroll
        for (int ks = 0; ks < 16; ks++) {
            qf[ks][0] = __float_as_uint(Qb[(size_t)lr * HID + ks * 8 + lc]);
            qf[ks][1] = __float_as_uint(Qb[(size_t)(lr + 8) * HID + ks * 8 + lc]);
            qf[ks][2] = __float_as_uint(Qb[(size_t)lr * HID + ks * 8 + lc + 4]);
            qf[ks][3] = __float_as_uint(Qb[(size_t)(lr + 8) * HID + ks * 8 + lc + 4]);
        }
    }

    float m0 = -1.0e30f, m1 = -1.0e30f, l0 = 0.0f, l1 = 0.0f;
    float of[16][4];
#pragma unroll
    for (int nt = 0; nt < 16; nt++)
#pragma unroll
        for (int i = 0; i < 4; i++) of[nt][i] = 0.0f;

    flash_load_kv(K, V, fsm, 0, 0, hcol, tid);
    CP_COMMIT();

    const int NT = SEQ / FSK;   // 32
    for (int kt = 0; kt < NT; kt++) {
        if (kt + 1 < NT) {
            flash_load_kv(K, V, fsm, (kt + 1) & 1, kt + 1, hcol, tid);
            CP_COMMIT();
            CP_WAIT(1);
        } else {
            CP_WAIT(0);
        }
        __syncthreads();

        const float* Ks = fsm + (kt & 1) * FSTAGE;
        const float* Vs = Ks + KTILE_FLOATS;
        const uint32_t ksa = smem_u32(Ks);

        float sf[8][4];
#pragma unroll
        for (int nt = 0; nt < 8; nt++)
#pragma unroll
            for (int i = 0; i < 4; i++) sf[nt][i] = 0.0f;

        // S = Q K^T : K fragments via ldmatrix.x4 (4 per k-step)
#pragma unroll
        for (int ks = 0; ks < 16; ks++) {
            uint32_t bf[8][2];
#pragma unroll
            for (int ng = 0; ng < 4; ng++) {
                uint32_t t[4];
                ldsm_x4(t, ksa + (uint32_t)((ng * 16 + l15) * KP + ks * 8 + lcol) * 4u);
                bf[2 * ng + 0][0] = t[0];
                bf[2 * ng + 1][0] = t[1];
                bf[2 * ng + 0][1] = t[2];
                bf[2 * ng + 1][1] = t[3];
            }
#pragma unroll
            for (int nt = 0; nt < 8; nt++)
                mma_tf32(sf[nt], qf[ks], bf[nt]);
        }

        float rmax0 = -1.0e30f, rmax1 = -1.0e30f;
#pragma unroll
        for (int nt = 0; nt < 8; nt++) {
            const float col0 = (float)(kt * FSK + nt * 8 + 2 * lc);
            sf[nt][0] = fmaf(sf[nt][0], alpha, obias * col0);
            sf[nt][1] = fmaf(sf[nt][1], alpha, obias * (col0 + 1.0f));
            sf[nt][2] = fmaf(sf[nt][2], alpha, obias * col0);
            sf[nt][3] = fmaf(sf[nt][3], alpha, obias * (col0 + 1.0f));
            rmax0 = fmaxf(rmax0, fmaxf(sf[nt][0], sf[nt][1]));
            rmax1 = fmaxf(rmax1, fmaxf(sf[nt][2], sf[nt][3]));
        }
#pragma unroll
        for (int off = 1; off < 4; off <<= 1) {
            rmax0 = fmaxf(rmax0, __shfl_xor_sync(0xffffffffu, rmax0, off));
            rmax1 = fmaxf(rmax1, __shfl_xor_sync(0xffffffffu, rmax1, off));
        }
        const float m0n = fmaxf(m0, rmax0);
        const float m1n = fmaxf(m1, rmax1);
        const float corr0 = __expf(m0 - m0n);
        const float corr1 = __expf(m1 - m1n);

        float rsum0 = 0.0f, rsum1 = 0.0f;
        uint32_t pf[8][4];
#pragma unroll
        for (int nt = 0; nt < 8; nt++) {
            const float e0 = __expf(sf[nt][0] - m0n);
            const float e1 = __expf(sf[nt][1] - m0n);
            const float e2 = __expf(sf[nt][2] - m1n);
            const float e3 = __expf(sf[nt][3] - m1n);
            rsum0 += e0 + e1;
            rsum1 += e2 + e3;
            pf[nt][0] = f2tf(e0); pf[nt][1] = f2tf(e1);
            pf[nt][2] = f2tf(e2); pf[nt][3] = f2tf(e3);
        }
#pragma unroll
        for (int off = 1; off < 4; off <<= 1) {
            rsum0 += __shfl_xor_sync(0xffffffffu, rsum0, off);
            rsum1 += __shfl_xor_sync(0xffffffffu, rsum1, off);
        }
        l0 = l0 * corr0 + rsum0; m0 = m0n;
        l1 = l1 * corr1 + rsum1; m1 = m1n;

#pragma unroll
        for (int nt = 0; nt < 16; nt++) {
            of[nt][0] *= corr0; of[nt][1] *= corr0;
            of[nt][2] *= corr1; of[nt][3] *= corr1;
        }

        const int src0 = lr * 4 + (lc >> 1);
        const bool odd = (lc & 1);
#pragma unroll
        for (int kp = 0; kp < 8; kp++) {
            uint32_t pa[4];
            {
                uint32_t v0 = shfl_u32(pf[kp][0], src0);
                uint32_t v1 = shfl_u32(pf[kp][1], src0);
                pa[0] = odd ? v1 : v0;
                uint32_t v2 = shfl_u32(pf[kp][2], src0);
                uint32_t v3 = shfl_u32(pf[kp][3], src0);
                pa[1] = odd ? v3 : v2;
                uint32_t w0 = shfl_u32(pf[kp][0], src0 + 2);
                uint32_t w1 = shfl_u32(pf[kp][1], src0 + 2);
                pa[2] = odd ? w1 : w0;
                uint32_t w2 = shfl_u32(pf[kp][2], src0 + 2);
                uint32_t w3 = shfl_u32(pf[kp][3], src0 + 2);
                pa[3] = odd ? w3 : w2;
            }
#pragma unroll
            for (int nt = 0; nt < 16; nt++) {
                uint32_t bf2[2];
                bf2[0] = __float_as_uint(Vs[(kp * 8 + lc) * VP + nt * 8 + lr]);
                bf2[1] = __float_as_uint(Vs[(kp * 8 + lc + 4) * VP + nt * 8 + lr]);
                mma_tf32(of[nt], pa, bf2);
            }
        }
        __syncthreads();
    }

    const float invl0 = 1.0f / l0;
    const float invl1 = 1.0f / l1;
    float* Ob = O + (size_t)qbase * HID + hcol;
#pragma unroll
    for (int nt = 0; nt < 16; nt++) {
        const int c = nt * 8 + 2 * lc;
        float2 v0, v1;
        v0.x = __uint_as_float(f2tf(of[nt][0] * invl0));
        v0.y = __uint_as_float(f2tf(of[nt][1] * invl0));
        v1.x = __uint_as_float(f2tf(of[nt][2] * invl1));
        v1.y = __uint_as_float(f2tf(of[nt][3] * invl1));
        *(float2*)(Ob + (size_t)lr * HID + c) = v0;
        *(float2*)(Ob + (size_t)(lr + 8) * HID + c) = v1;
    }
}

// ===========================================================================
extern "C" void kernel_launch(void* const* d_in, const int* in_sizes, int n_in,
                              void* d_out, int out_size)
{
    const float* X  = (const float*)d_in[0];
    const float* Wq = (const float*)d_in[1];
    const float* bq = (const float*)d_in[2];
    const float* Wk = (const float*)d_in[3];
    const float* bk = (const float*)d_in[4];
    const float* Wv = (const float*)d_in[5];
    const float* bv = (const float*)d_in[6];
    const float* Wo = (const float*)d_in[7];
    const float* bo = (const float*)d_in[8];
    const float* order_gate   = (const float*)d_in[11];
    const float* justice_gate = (const float*)d_in[12];
    float* out = (float*)d_out;

    float *qp, *kp, *vp, *op, *xr, *w0, *w1, *w2, *w3;
    cudaGetSymbolAddress((void**)&qp, g_Q);
    cudaGetSymbolAddress((void**)&kp, g_K);
    cudaGetSymbolAddress((void**)&vp, g_V);
    cudaGetSymbolAddress((void**)&op, g_O);
    cudaGetSymbolAddress((void**)&xr, g_Xr);
    cudaGetSymbolAddress((void**)&w0, g_W0);
    cudaGetSymbolAddress((void**)&w1, g_W1);
    cudaGetSymbolAddress((void**)&w2, g_W2);
    cudaGetSymbolAddress((void**)&w3, g_W3);

    cudaFuncSetAttribute(gemm_qkv,
                         cudaFuncAttributeMaxDynamicSharedMemorySize,
                         GEMM_SMEM_BYTES);
    cudaFuncSetAttribute(gemm_single,
                         cudaFuncAttributeMaxDynamicSharedMemorySize,
                         GEMM_SMEM_BYTES);
    cudaFuncSetAttribute(flash_attn_tf32,
                         cudaFuncAttributeMaxDynamicSharedMemorySize,
                         FLASH_SMEM_BYTES);

    const int N4 = (HID * HID) / 4;
    const dim3 rg((N4 + 255) / 256);

    // prepass: round inputs to tf32 once
    round_tf32<<<rg, 256>>>((const float4*)X,  (float4*)xr, N4);
    round_tf32<<<rg, 256>>>((const float4*)Wq, (float4*)w0, N4);
    round_tf32<<<rg, 256>>>((const float4*)Wk, (float4*)w1, N4);
    round_tf32<<<rg, 256>>>((const float4*)Wv, (float4*)w2, N4);
    round_tf32<<<rg, 256>>>((const float4*)Wo, (float4*)w3, N4);

    // fused QKV projections (one launch, z = 0/1/2)
    dim3 gq(HID / BN, SEQ / BM, 3);
    gemm_qkv<<<gq, 256, GEMM_SMEM_BYTES>>>(xr, w0, w1, w2, bq, bk, bv,
                                           qp, kp, vp);

    dim3 ga(SEQ / FAQ, NH);        // 16 x 16
    flash_attn_tf32<<<ga, 256, FLASH_SMEM_BYTES>>>(qp, kp, vp, op,
                                                   order_gate, justice_gate);

    dim3 gg(HID / BN, SEQ / BM);   // 16 x 16
    gemm_single<<<gg, 256, GEMM_SMEM_BYTES>>>(op, w3, bo, out);
}